// round 1
// baseline (speedup 1.0000x reference)
#include <cuda_runtime.h>
#include <math.h>

// Problem constants
#define T_STEPS 512
#define BATCH   64
#define DIM     1024
#define HID     1024
#define GATES   (4 * HID)   // 4096

// Scratch (allocation-free rule: __device__ globals)
__device__ float g_xg[(size_t)T_STEPS * BATCH * GATES];  // 512 MB: precomputed x@Wi + b
__device__ float g_c[BATCH * HID];                       // cell state

// ---------------------------------------------------------------------------
// Kernel 1: xg = x @ Wi + b
// A [M=32768, K=1024] row-major, B [K=1024, N=4096] row-major, C = g_xg [M, N]
// Classic 128x128x8 SGEMM, 256 threads, 8x8 per-thread microtile.
// ---------------------------------------------------------------------------
__global__ __launch_bounds__(256) void xg_gemm(const float* __restrict__ A,
                                               const float* __restrict__ Bm,
                                               const float* __restrict__ bias) {
    const int N = GATES, K = DIM;
    __shared__ float As[8][132];  // padded: avoids transpose-store bank conflicts
    __shared__ float Bs[8][128];

    int tid = threadIdx.x;
    int bm = blockIdx.y * 128;
    int bn = blockIdx.x * 128;

    // Load mappings (one float4 per thread per tile per operand)
    int a_row = tid >> 1;          // 0..127
    int a_col = (tid & 1) * 4;     // 0 or 4
    int b_row = tid >> 5;          // 0..7
    int b_col = (tid & 31) * 4;    // 0..124

    // Compute mapping: 16x16 threads, 8x8 microtile
    int ty = (tid >> 4) * 8;
    int tx = (tid & 15) * 8;

    float acc[8][8];
#pragma unroll
    for (int i = 0; i < 8; i++)
#pragma unroll
        for (int j = 0; j < 8; j++) acc[i][j] = 0.f;

    const float* Aptr = A + (size_t)(bm + a_row) * K + a_col;
    const float* Bptr = Bm + (size_t)b_row * N + bn + b_col;

    for (int k0 = 0; k0 < K; k0 += 8) {
        float4 av = *(const float4*)(Aptr + k0);
        float4 bv = *(const float4*)(Bptr + (size_t)k0 * N);
        As[a_col + 0][a_row] = av.x;
        As[a_col + 1][a_row] = av.y;
        As[a_col + 2][a_row] = av.z;
        As[a_col + 3][a_row] = av.w;
        *(float4*)&Bs[b_row][b_col] = bv;
        __syncthreads();

#pragma unroll
        for (int kk = 0; kk < 8; kk++) {
            float ar[8], br[8];
            *(float4*)&ar[0] = *(const float4*)&As[kk][ty];
            *(float4*)&ar[4] = *(const float4*)&As[kk][ty + 4];
            *(float4*)&br[0] = *(const float4*)&Bs[kk][tx];
            *(float4*)&br[4] = *(const float4*)&Bs[kk][tx + 4];
#pragma unroll
            for (int i = 0; i < 8; i++)
#pragma unroll
                for (int j = 0; j < 8; j++)
                    acc[i][j] = fmaf(ar[i], br[j], acc[i][j]);
        }
        __syncthreads();
    }

#pragma unroll
    for (int i = 0; i < 8; i++) {
        size_t crow = (size_t)(bm + ty + i) * N + bn + tx;
#pragma unroll
        for (int j = 0; j < 8; j++)
            g_xg[crow + j] = acc[i][j] + bias[bn + tx + j];
    }
}

// ---------------------------------------------------------------------------
// Kernel 2: one LSTM timestep, fully fused.
// gates = xg[t] + h_prev @ Wh ; i,f,o = sigmoid, g = tanh
// c = f*c + i*g ; h = o*tanh(c)
// Tile: 32 batch rows (blockIdx.y) x 16 h-cols (blockIdx.x) x 4 gates.
// Grid = (64, 2) = 128 CTAs, 128 threads. Each thread owns 4 batch rows x
// 1 h-col x all 4 gates -> epilogue needs no cross-thread communication.
// ---------------------------------------------------------------------------
__global__ __launch_bounds__(128) void lstm_step(int t,
                                                 const float* __restrict__ h0,
                                                 const float* __restrict__ c0,
                                                 const float* __restrict__ Wh,
                                                 float* __restrict__ out) {
    __shared__ float As[16][33];  // [k][b], padded
    __shared__ float Bs[16][64];  // [k][g*16 + c]

    const float* h_prev = (t == 0) ? h0 : (out + (size_t)(t - 1) * BATCH * HID);
    const float* c_prev = (t == 0) ? c0 : g_c;
    const float* xg_t = g_xg + (size_t)t * BATCH * GATES;

    int tid = threadIdx.x;
    int bm = blockIdx.y * 32;
    int hc0 = blockIdx.x * 16;

    // A load: b = tid/4 (0..31), kc = (tid%4)*4 -> one float4 per thread/tile
    int lb = tid >> 2;
    int lkc = (tid & 3) * 4;

    // Compute mapping
    int tb = tid >> 4;    // 0..7 -> 4 batch rows each
    int thc = tid & 15;   // 0..15 h-col within tile

    float acc[4][4];
#pragma unroll
    for (int i = 0; i < 4; i++)
#pragma unroll
        for (int j = 0; j < 4; j++) acc[i][j] = 0.f;

    for (int k0 = 0; k0 < DIM; k0 += 16) {
        // Load h_prev tile (32 x 16), transposed into As
        float4 av = *(const float4*)(h_prev + (size_t)(bm + lb) * HID + k0 + lkc);
        As[lkc + 0][lb] = av.x;
        As[lkc + 1][lb] = av.y;
        As[lkc + 2][lb] = av.z;
        As[lkc + 3][lb] = av.w;

        // Load Wh tile: 16 k-rows x (4 gates x 16 h-cols) = 256 float4 / 128 thr
#pragma unroll
        for (int u = 0; u < 2; u++) {
            int idx = tid * 2 + u;       // 0..255
            int kr = idx >> 4;           // 0..15
            int rem = idx & 15;
            int gg = rem >> 2;           // gate 0..3
            int c4 = (rem & 3) * 4;      // 0,4,8,12
            float4 bv = *(const float4*)(Wh + (size_t)(k0 + kr) * GATES +
                                         gg * HID + hc0 + c4);
            *(float4*)&Bs[kr][gg * 16 + c4] = bv;
        }
        __syncthreads();

#pragma unroll
        for (int kk = 0; kk < 16; kk++) {
            float ar[4], br[4];
#pragma unroll
            for (int bi = 0; bi < 4; bi++) ar[bi] = As[kk][tb * 4 + bi];
#pragma unroll
            for (int gg = 0; gg < 4; gg++) br[gg] = Bs[kk][gg * 16 + thc];
#pragma unroll
            for (int bi = 0; bi < 4; bi++)
#pragma unroll
                for (int gg = 0; gg < 4; gg++)
                    acc[bi][gg] = fmaf(ar[bi], br[gg], acc[bi][gg]);
        }
        __syncthreads();
    }

    int hcol = hc0 + thc;
    float* h_out = out + (size_t)t * BATCH * HID;
#pragma unroll
    for (int bi = 0; bi < 4; bi++) {
        int b = bm + tb * 4 + bi;
        const float* xgp = xg_t + (size_t)b * GATES;
        float iv = acc[bi][0] + xgp[hcol];
        float fv = acc[bi][1] + xgp[HID + hcol];
        float gv = acc[bi][2] + xgp[2 * HID + hcol];
        float ov = acc[bi][3] + xgp[3 * HID + hcol];
        iv = 1.f / (1.f + expf(-iv));
        fv = 1.f / (1.f + expf(-fv));
        gv = tanhf(gv);
        ov = 1.f / (1.f + expf(-ov));
        float cv = fv * c_prev[(size_t)b * HID + hcol] + iv * gv;
        float hv = ov * tanhf(cv);
        g_c[(size_t)b * HID + hcol] = cv;
        h_out[(size_t)b * HID + hcol] = hv;
    }
}

// ---------------------------------------------------------------------------
extern "C" void kernel_launch(void* const* d_in, const int* in_sizes, int n_in,
                              void* d_out, int out_size) {
    const float* x  = (const float*)d_in[0];   // [T, B, D]
    const float* c0 = (const float*)d_in[1];   // [B, H]
    const float* h0 = (const float*)d_in[2];   // [B, H]
    const float* Wi = (const float*)d_in[3];   // [D, 4H]
    const float* Wh = (const float*)d_in[4];   // [H, 4H]
    const float* b  = (const float*)d_in[5];   // [4H]
    float* out = (float*)d_out;                // [T, B, H]

    // 1. Precompute input projection for all timesteps: one big GEMM.
    dim3 g1(GATES / 128, (T_STEPS * BATCH) / 128);  // (32, 256)
    xg_gemm<<<g1, 256>>>(x, Wi, b);

    // 2. Sequential recurrence: one fused kernel per timestep.
    dim3 g2(HID / 16, BATCH / 32);  // (64, 2) = 128 CTAs
    for (int t = 0; t < T_STEPS; t++) {
        lstm_step<<<g2, 128>>>(t, h0, c0, Wh, out);
    }
}

// round 3
// speedup vs baseline: 2.6726x; 2.6726x over previous
#include <cuda_runtime.h>
#include <math.h>
#include <stdint.h>

#define T_STEPS 512
#define BATCH   64
#define DIM     1024
#define HID     1024
#define GATES   4096

// Scratch (__device__ globals: allocation-free rule)
__device__ float    g_xg[(size_t)T_STEPS * BATCH * GATES]; // x@Wi + b
__device__ float    g_c[BATCH * HID];                      // cell state
__device__ uint32_t g_wr[(size_t)DIM * GATES];             // Wh reordered, tf32 bits, [k][col']

// ---------------------------------------------------------------------------
// Helpers: tf32 convert + portable tensor-core mma (sm_80+ PTX, works on
// compute_103 target — tcgen05 is NOT available at this PTX target).
// ---------------------------------------------------------------------------
__device__ __forceinline__ uint32_t f2tf(float v) {
    uint32_t u;
    asm("cvt.rna.tf32.f32 %0, %1;" : "=r"(u) : "f"(v));
    return u;
}

// D(16x8) += A(16x8) * B(8x8); tf32 inputs, fp32 accum.
__device__ __forceinline__ void mma_tf32(float* c,
                                         uint32_t a0, uint32_t a1, uint32_t a2, uint32_t a3,
                                         uint32_t b0, uint32_t b1) {
    asm volatile(
        "mma.sync.aligned.m16n8k8.row.col.f32.tf32.tf32.f32 "
        "{%0,%1,%2,%3}, {%4,%5,%6,%7}, {%8,%9}, {%0,%1,%2,%3};"
        : "+f"(c[0]), "+f"(c[1]), "+f"(c[2]), "+f"(c[3])
        : "r"(a0), "r"(a1), "r"(a2), "r"(a3), "r"(b0), "r"(b1));
}

// ---------------------------------------------------------------------------
// Kernel 0: reorder Wh[k][g*1024 + c*8 + j] -> g_wr[k][c*32 + g*8 + j], tf32.
// Gate-interleaved so one CTA's 32 output cols = 8 h-cols x 4 gates.
// ---------------------------------------------------------------------------
__global__ __launch_bounds__(256) void wr_prep(const float* __restrict__ Wh) {
    int idx = blockIdx.x * 256 + threadIdx.x;   // k*4096 + col
    int col = idx & 4095;
    int k   = idx >> 12;
    int g = col >> 10, rem = col & 1023, c = rem >> 3, j = rem & 7;
    g_wr[(size_t)k * GATES + c * 32 + g * 8 + j] = f2tf(Wh[idx]);
}

// ---------------------------------------------------------------------------
// Kernel 1: xg = x @ Wi + b via tf32 mma.sync.
// CTA tile 128x128, 256 thr = 8 warps, warp tile 32x64 (2 m-frags x 8 n-frags).
// K-chunk 32, register-prefetch double buffering of global loads.
// ---------------------------------------------------------------------------
__global__ __launch_bounds__(256) void xg_gemm_mma(const float* __restrict__ x,
                                                   const float* __restrict__ Wi,
                                                   const float* __restrict__ bias) {
    __shared__ uint32_t As[128][36];   // [m][k], pad 4 (conflict-free frag reads)
    __shared__ uint32_t Bs[32][132];   // [k][n], pad 4

    int tid = threadIdx.x, wid = tid >> 5, lane = tid & 31;
    int gid = lane >> 2, tig = lane & 3;
    int bm = blockIdx.y * 128, bn = blockIdx.x * 128;
    int wrow = (wid & 3) * 32, wcol = (wid >> 2) * 64;

    float acc[2][8][4];
#pragma unroll
    for (int i = 0; i < 2; i++)
#pragma unroll
        for (int j = 0; j < 8; j++)
#pragma unroll
            for (int k = 0; k < 4; k++) acc[i][j][k] = 0.f;

    float4 pa[4], pb[4];

    // prefetch chunk 0
#pragma unroll
    for (int u = 0; u < 4; u++) {
        int s = u * 256 + tid, r = s >> 3, c = (s & 7) * 4;
        pa[u] = *(const float4*)(x + (size_t)(bm + r) * DIM + c);
    }
#pragma unroll
    for (int u = 0; u < 4; u++) {
        int s = u * 256 + tid, r = s >> 5, c = (s & 31) * 4;
        pb[u] = *(const float4*)(Wi + (size_t)r * GATES + bn + c);
    }

    for (int k0 = 0; k0 < DIM; k0 += 32) {
        // store current chunk (convert to tf32)
#pragma unroll
        for (int u = 0; u < 4; u++) {
            int s = u * 256 + tid, r = s >> 3, c = (s & 7) * 4;
            As[r][c + 0] = f2tf(pa[u].x); As[r][c + 1] = f2tf(pa[u].y);
            As[r][c + 2] = f2tf(pa[u].z); As[r][c + 3] = f2tf(pa[u].w);
        }
#pragma unroll
        for (int u = 0; u < 4; u++) {
            int s = u * 256 + tid, r = s >> 5, c = (s & 31) * 4;
            Bs[r][c + 0] = f2tf(pb[u].x); Bs[r][c + 1] = f2tf(pb[u].y);
            Bs[r][c + 2] = f2tf(pb[u].z); Bs[r][c + 3] = f2tf(pb[u].w);
        }
        __syncthreads();

        // prefetch next chunk (overlaps mma)
        if (k0 + 32 < DIM) {
#pragma unroll
            for (int u = 0; u < 4; u++) {
                int s = u * 256 + tid, r = s >> 3, c = (s & 7) * 4;
                pa[u] = *(const float4*)(x + (size_t)(bm + r) * DIM + k0 + 32 + c);
            }
#pragma unroll
            for (int u = 0; u < 4; u++) {
                int s = u * 256 + tid, r = s >> 5, c = (s & 31) * 4;
                pb[u] = *(const float4*)(Wi + (size_t)(k0 + 32 + r) * GATES + bn + c);
            }
        }

#pragma unroll
        for (int kk = 0; kk < 4; kk++) {
            int kb = kk * 8;
            uint32_t a[2][4];
#pragma unroll
            for (int mf = 0; mf < 2; mf++) {
                int m = wrow + mf * 16 + gid;
                a[mf][0] = As[m][kb + tig];
                a[mf][1] = As[m + 8][kb + tig];
                a[mf][2] = As[m][kb + tig + 4];
                a[mf][3] = As[m + 8][kb + tig + 4];
            }
#pragma unroll
            for (int nf = 0; nf < 8; nf++) {
                uint32_t b0 = Bs[kb + tig][wcol + nf * 8 + gid];
                uint32_t b1 = Bs[kb + tig + 4][wcol + nf * 8 + gid];
                mma_tf32(acc[0][nf], a[0][0], a[0][1], a[0][2], a[0][3], b0, b1);
                mma_tf32(acc[1][nf], a[1][0], a[1][1], a[1][2], a[1][3], b0, b1);
            }
        }
        __syncthreads();
    }

#pragma unroll
    for (int mf = 0; mf < 2; mf++)
#pragma unroll
        for (int nf = 0; nf < 8; nf++) {
            int row = bm + wrow + mf * 16 + gid;
            int col = bn + wcol + nf * 8 + 2 * tig;
            float bv0 = bias[col], bv1 = bias[col + 1];
            g_xg[(size_t)row * GATES + col]           = acc[mf][nf][0] + bv0;
            g_xg[(size_t)row * GATES + col + 1]       = acc[mf][nf][1] + bv1;
            g_xg[(size_t)(row + 8) * GATES + col]     = acc[mf][nf][2] + bv0;
            g_xg[(size_t)(row + 8) * GATES + col + 1] = acc[mf][nf][3] + bv1;
        }
}

// ---------------------------------------------------------------------------
// Kernel 2: one LSTM step via tf32 mma.sync.
// 128 CTAs x 128 thr. CTA c: M=64 (all batch), N=32 = 8 h-cols x 4 gates
// (gate-interleaved g_wr), so n-frag nf == gate nf for the same h-cols ->
// fused epilogue with zero cross-thread traffic.
// ---------------------------------------------------------------------------
__global__ __launch_bounds__(128) void lstm_step_mma(int t,
                                                     const float* __restrict__ h0,
                                                     const float* __restrict__ c0,
                                                     float* __restrict__ out) {
    __shared__ uint32_t As[64][68];   // [m=batch][k], pad 4
    __shared__ uint32_t Bs[64][36];   // [k][n=32], pad 4

    int tid = threadIdx.x, wid = tid >> 5, lane = tid & 31;
    int gid = lane >> 2, tig = lane & 3;
    int cta = blockIdx.x;
    int n0 = cta * 32;

    const float* h_prev = t ? out + (size_t)(t - 1) * BATCH * HID : h0;
    const float* c_prev = t ? g_c : c0;
    const float* xg_t = g_xg + (size_t)t * BATCH * GATES;

    float acc[4][4];
#pragma unroll
    for (int i = 0; i < 4; i++)
#pragma unroll
        for (int j = 0; j < 4; j++) acc[i][j] = 0.f;

    float4 pa[8];
    uint4  pb[4];

    // prefetch chunk 0 (K-chunk = 64)
#pragma unroll
    for (int u = 0; u < 8; u++) {
        int s = u * 128 + tid, r = s >> 4, c = (s & 15) * 4;
        pa[u] = *(const float4*)(h_prev + (size_t)r * HID + c);
    }
#pragma unroll
    for (int u = 0; u < 4; u++) {
        int s = u * 128 + tid, r = s >> 3, c = (s & 7) * 4;
        pb[u] = *(const uint4*)(g_wr + (size_t)r * GATES + n0 + c);
    }

    for (int k0 = 0; k0 < DIM; k0 += 64) {
#pragma unroll
        for (int u = 0; u < 8; u++) {
            int s = u * 128 + tid, r = s >> 4, c = (s & 15) * 4;
            uint4 av;
            av.x = f2tf(pa[u].x); av.y = f2tf(pa[u].y);
            av.z = f2tf(pa[u].z); av.w = f2tf(pa[u].w);
            *(uint4*)&As[r][c] = av;
        }
#pragma unroll
        for (int u = 0; u < 4; u++) {
            int s = u * 128 + tid, r = s >> 3, c = (s & 7) * 4;
            *(uint4*)&Bs[r][c] = pb[u];
        }
        __syncthreads();

        if (k0 + 64 < DIM) {
#pragma unroll
            for (int u = 0; u < 8; u++) {
                int s = u * 128 + tid, r = s >> 4, c = (s & 15) * 4;
                pa[u] = *(const float4*)(h_prev + (size_t)r * HID + k0 + 64 + c);
            }
#pragma unroll
            for (int u = 0; u < 4; u++) {
                int s = u * 128 + tid, r = s >> 3, c = (s & 7) * 4;
                pb[u] = *(const uint4*)(g_wr + (size_t)(k0 + 64 + r) * GATES + n0 + c);
            }
        }

#pragma unroll
        for (int kk = 0; kk < 8; kk++) {
            int kb = kk * 8;
            int m = wid * 16 + gid;
            uint32_t a0 = As[m][kb + tig];
            uint32_t a1 = As[m + 8][kb + tig];
            uint32_t a2 = As[m][kb + tig + 4];
            uint32_t a3 = As[m + 8][kb + tig + 4];
#pragma unroll
            for (int nf = 0; nf < 4; nf++) {
                uint32_t b0 = Bs[kb + tig][nf * 8 + gid];
                uint32_t b1 = Bs[kb + tig + 4][nf * 8 + gid];
                mma_tf32(acc[nf], a0, a1, a2, a3, b0, b1);
            }
        }
        __syncthreads();
    }

    // fused LSTM epilogue: n-frag index == gate index, same (row, col) pair
    int r0 = wid * 16 + gid;
    int hc = cta * 8 + 2 * tig;
    float* h_out = out + (size_t)t * BATCH * HID;
#pragma unroll
    for (int rr = 0; rr < 2; rr++) {
        int r = r0 + rr * 8;
        const float* xgp = xg_t + (size_t)r * GATES;
#pragma unroll
        for (int cc = 0; cc < 2; cc++) {
            int col = hc + cc;
            int ci = rr * 2 + cc;
            float iv = acc[0][ci] + xgp[col];
            float fv = acc[1][ci] + xgp[1024 + col];
            float gv = acc[2][ci] + xgp[2048 + col];
            float ov = acc[3][ci] + xgp[3072 + col];
            iv = 1.f / (1.f + expf(-iv));
            fv = 1.f / (1.f + expf(-fv));
            gv = tanhf(gv);
            ov = 1.f / (1.f + expf(-ov));
            float cv = fv * c_prev[(size_t)r * HID + col] + iv * gv;
            g_c[(size_t)r * HID + col] = cv;
            h_out[(size_t)r * HID + col] = ov * tanhf(cv);
        }
    }
}

// ---------------------------------------------------------------------------
extern "C" void kernel_launch(void* const* d_in, const int* in_sizes, int n_in,
                              void* d_out, int out_size) {
    const float* x  = (const float*)d_in[0];   // [T, B, D]
    const float* c0 = (const float*)d_in[1];   // [B, H]
    const float* h0 = (const float*)d_in[2];   // [B, H]
    const float* Wi = (const float*)d_in[3];   // [D, 4H]
    const float* Wh = (const float*)d_in[4];   // [H, 4H]
    const float* b  = (const float*)d_in[5];   // [4H]
    float* out = (float*)d_out;                // [T, B, H]

    // Reorder + tf32-round Wh
    wr_prep<<<(DIM * GATES) / 256, 256>>>(Wh);

    // Input projection (tf32 tensor cores)
    dim3 g1(GATES / 128, (T_STEPS * BATCH) / 128);  // (32, 256)
    xg_gemm_mma<<<g1, 256>>>(x, Wi, b);

    // Recurrence
    for (int t = 0; t < T_STEPS; t++) {
        lstm_step_mma<<<128, 128>>>(t, h0, c0, out);
    }
}

// round 4
// speedup vs baseline: 3.6195x; 1.3543x over previous
#include <cuda_runtime.h>
#include <math.h>
#include <stdint.h>

#define T_STEPS 512
#define BATCH   64
#define DIM     1024
#define HID     1024
#define GATES   4096
#define NCTA    128

// Scratch (__device__ globals: allocation-free rule)
__device__ float    g_xg[(size_t)T_STEPS * BATCH * GATES]; // x@Wi + b
__device__ uint32_t g_wr[(size_t)DIM * GATES];             // Wh reordered, tf32 bits, [k][col']
__device__ unsigned g_bar;                                 // grid barrier counter

// ---------------------------------------------------------------------------
// Helpers
// ---------------------------------------------------------------------------
__device__ __forceinline__ uint32_t f2tf(float v) {
    uint32_t u;
    asm("cvt.rna.tf32.f32 %0, %1;" : "=r"(u) : "f"(v));
    return u;
}

__device__ __forceinline__ void mma_tf32(float* c,
                                         uint32_t a0, uint32_t a1, uint32_t a2, uint32_t a3,
                                         uint32_t b0, uint32_t b1) {
    asm volatile(
        "mma.sync.aligned.m16n8k8.row.col.f32.tf32.tf32.f32 "
        "{%0,%1,%2,%3}, {%4,%5,%6,%7}, {%8,%9}, {%0,%1,%2,%3};"
        : "+f"(c[0]), "+f"(c[1]), "+f"(c[2]), "+f"(c[3])
        : "r"(a0), "r"(a1), "r"(a2), "r"(a3), "r"(b0), "r"(b1));
}

__device__ __forceinline__ unsigned ld_acq(const unsigned* p) {
    unsigned v;
    asm volatile("ld.acquire.gpu.global.u32 %0, [%1];" : "=r"(v) : "l"(p));
    return v;
}

// ---------------------------------------------------------------------------
// Kernel 0: reorder Wh[k][g*1024 + c*8 + j] -> g_wr[k][c*32 + g*8 + j], tf32.
// Also zeroes the grid-barrier counter (every launch -> replay-deterministic).
// ---------------------------------------------------------------------------
__global__ __launch_bounds__(256) void wr_prep(const float* __restrict__ Wh) {
    if (blockIdx.x == 0 && threadIdx.x == 0) g_bar = 0;
    int idx = blockIdx.x * 256 + threadIdx.x;   // k*4096 + col
    int col = idx & 4095;
    int k   = idx >> 12;
    int g = col >> 10, rem = col & 1023, c = rem >> 3, j = rem & 7;
    g_wr[(size_t)k * GATES + c * 32 + g * 8 + j] = f2tf(Wh[idx]);
}

// ---------------------------------------------------------------------------
// Kernel 1: xg = x @ Wi + b via tf32 mma.sync (unchanged from R3).
// ---------------------------------------------------------------------------
__global__ __launch_bounds__(256) void xg_gemm_mma(const float* __restrict__ x,
                                                   const float* __restrict__ Wi,
                                                   const float* __restrict__ bias) {
    __shared__ uint32_t As[128][36];
    __shared__ uint32_t Bs[32][132];

    int tid = threadIdx.x, wid = tid >> 5, lane = tid & 31;
    int gid = lane >> 2, tig = lane & 3;
    int bm = blockIdx.y * 128, bn = blockIdx.x * 128;
    int wrow = (wid & 3) * 32, wcol = (wid >> 2) * 64;

    float acc[2][8][4];
#pragma unroll
    for (int i = 0; i < 2; i++)
#pragma unroll
        for (int j = 0; j < 8; j++)
#pragma unroll
            for (int k = 0; k < 4; k++) acc[i][j][k] = 0.f;

    float4 pa[4], pb[4];

#pragma unroll
    for (int u = 0; u < 4; u++) {
        int s = u * 256 + tid, r = s >> 3, c = (s & 7) * 4;
        pa[u] = *(const float4*)(x + (size_t)(bm + r) * DIM + c);
    }
#pragma unroll
    for (int u = 0; u < 4; u++) {
        int s = u * 256 + tid, r = s >> 5, c = (s & 31) * 4;
        pb[u] = *(const float4*)(Wi + (size_t)r * GATES + bn + c);
    }

    for (int k0 = 0; k0 < DIM; k0 += 32) {
#pragma unroll
        for (int u = 0; u < 4; u++) {
            int s = u * 256 + tid, r = s >> 3, c = (s & 7) * 4;
            As[r][c + 0] = f2tf(pa[u].x); As[r][c + 1] = f2tf(pa[u].y);
            As[r][c + 2] = f2tf(pa[u].z); As[r][c + 3] = f2tf(pa[u].w);
        }
#pragma unroll
        for (int u = 0; u < 4; u++) {
            int s = u * 256 + tid, r = s >> 5, c = (s & 31) * 4;
            Bs[r][c + 0] = f2tf(pb[u].x); Bs[r][c + 1] = f2tf(pb[u].y);
            Bs[r][c + 2] = f2tf(pb[u].z); Bs[r][c + 3] = f2tf(pb[u].w);
        }
        __syncthreads();

        if (k0 + 32 < DIM) {
#pragma unroll
            for (int u = 0; u < 4; u++) {
                int s = u * 256 + tid, r = s >> 3, c = (s & 7) * 4;
                pa[u] = *(const float4*)(x + (size_t)(bm + r) * DIM + k0 + 32 + c);
            }
#pragma unroll
            for (int u = 0; u < 4; u++) {
                int s = u * 256 + tid, r = s >> 5, c = (s & 31) * 4;
                pb[u] = *(const float4*)(Wi + (size_t)(k0 + 32 + r) * GATES + bn + c);
            }
        }

#pragma unroll
        for (int kk = 0; kk < 4; kk++) {
            int kb = kk * 8;
            uint32_t a[2][4];
#pragma unroll
            for (int mf = 0; mf < 2; mf++) {
                int m = wrow + mf * 16 + gid;
                a[mf][0] = As[m][kb + tig];
                a[mf][1] = As[m + 8][kb + tig];
                a[mf][2] = As[m][kb + tig + 4];
                a[mf][3] = As[m + 8][kb + tig + 4];
            }
#pragma unroll
            for (int nf = 0; nf < 8; nf++) {
                uint32_t b0 = Bs[kb + tig][wcol + nf * 8 + gid];
                uint32_t b1 = Bs[kb + tig + 4][wcol + nf * 8 + gid];
                mma_tf32(acc[0][nf], a[0][0], a[0][1], a[0][2], a[0][3], b0, b1);
                mma_tf32(acc[1][nf], a[1][0], a[1][1], a[1][2], a[1][3], b0, b1);
            }
        }
        __syncthreads();
    }

#pragma unroll
    for (int mf = 0; mf < 2; mf++)
#pragma unroll
        for (int nf = 0; nf < 8; nf++) {
            int row = bm + wrow + mf * 16 + gid;
            int col = bn + wcol + nf * 8 + 2 * tig;
            float bv0 = bias[col], bv1 = bias[col + 1];
            g_xg[(size_t)row * GATES + col]           = acc[mf][nf][0] + bv0;
            g_xg[(size_t)row * GATES + col + 1]       = acc[mf][nf][1] + bv1;
            g_xg[(size_t)(row + 8) * GATES + col]     = acc[mf][nf][2] + bv0;
            g_xg[(size_t)(row + 8) * GATES + col + 1] = acc[mf][nf][3] + bv1;
        }
}

// ---------------------------------------------------------------------------
// Kernel 2: PERSISTENT recurrence. 128 CTAs x 256 thr; all 512 steps in one
// launch, Wh slice resident in SMEM, c in registers, grid barrier per step.
// Warps 0-3: M-strips (16 rows each), K-even; warps 4-7: same strips, K-odd.
// ---------------------------------------------------------------------------
#define BRL 1028                 // BsT row length (words); 1028 % 32 == 4 -> conflict-free
#define ARL 132                  // As row length (words);  132 % 32 == 4
#define BSZ (32 * BRL)           // 32896 words
#define ASZ (64 * ARL)           // 8448 words
#define PERSIST_SMEM ((BSZ + ASZ) * 4)   // 165376 bytes

__global__ __launch_bounds__(256, 1) void lstm_persist(const float* __restrict__ h0,
                                                       const float* __restrict__ c0,
                                                       float* __restrict__ out) {
    extern __shared__ uint32_t sm[];
    uint32_t* BsT = sm;          // [n=32][k=1024] padded
    uint32_t* As  = sm + BSZ;    // [m=64][k_chunk=128] padded
    float* red = (float*)As;     // reduction buffer (reused between steps)

    int tid = threadIdx.x, wid = tid >> 5, lane = tid & 31;
    int gid = lane >> 2, tig = lane & 3;
    int cta = blockIdx.x;
    int mstrip = wid & 3, kpar = wid >> 2;
    int n0 = cta * 32;

    // Load resident B slice: BsT[n][k] = g_wr[k][n0+n]
    for (int s = tid; s < 1024 * 8; s += 256) {
        int k = s >> 3, c4 = (s & 7) * 4;
        uint4 v = *(const uint4*)(g_wr + (size_t)k * GATES + n0 + c4);
        BsT[(c4 + 0) * BRL + k] = v.x;
        BsT[(c4 + 1) * BRL + k] = v.y;
        BsT[(c4 + 2) * BRL + k] = v.z;
        BsT[(c4 + 3) * BRL + k] = v.w;
    }

    int r0 = mstrip * 16 + gid;
    int hc = cta * 8 + 2 * tig;

    // c state lives in registers (warps 0-3 only)
    float creg[4];
    if (wid < 4) {
#pragma unroll
        for (int rr = 0; rr < 2; rr++)
#pragma unroll
            for (int cc = 0; cc < 2; cc++)
                creg[rr * 2 + cc] = c0[(size_t)(r0 + rr * 8) * HID + hc + cc];
    }
    __syncthreads();

    for (int t = 0; t < T_STEPS; t++) {
        const float* h_prev = t ? out + (size_t)(t - 1) * BATCH * HID : h0;
        const float* xg_t = g_xg + (size_t)t * BATCH * GATES;

        // Prefetch this step's xg slice into registers (hides DRAM latency)
        float xv[16];
        if (wid < 4) {
#pragma unroll
            for (int g = 0; g < 4; g++)
#pragma unroll
                for (int rr = 0; rr < 2; rr++)
#pragma unroll
                    for (int cc = 0; cc < 2; cc++)
                        xv[g * 4 + rr * 2 + cc] =
                            xg_t[(size_t)(r0 + rr * 8) * GATES + g * 1024 + hc + cc];
        }

        float acc[4][4];
#pragma unroll
        for (int i = 0; i < 4; i++)
#pragma unroll
            for (int j = 0; j < 4; j++) acc[i][j] = 0.f;

        // Prefetch A chunk 0 (h_prev rows, K columns [0,128))
        float4 pa[8];
#pragma unroll
        for (int u = 0; u < 8; u++) {
            int idx = u * 256 + tid, r = idx >> 5, c = (idx & 31) * 4;
            pa[u] = *(const float4*)(h_prev + (size_t)r * HID + c);
        }

        for (int ch = 0; ch < 8; ch++) {
            // store current chunk (tf32 convert)
#pragma unroll
            for (int u = 0; u < 8; u++) {
                int idx = u * 256 + tid, r = idx >> 5, c = (idx & 31) * 4;
                uint4 av;
                av.x = f2tf(pa[u].x); av.y = f2tf(pa[u].y);
                av.z = f2tf(pa[u].z); av.w = f2tf(pa[u].w);
                *(uint4*)&As[r * ARL + c] = av;
            }
            __syncthreads();

            // prefetch next chunk (overlaps MMA)
            if (ch < 7) {
#pragma unroll
                for (int u = 0; u < 8; u++) {
                    int idx = u * 256 + tid, r = idx >> 5, c = (idx & 31) * 4;
                    pa[u] = *(const float4*)(h_prev + (size_t)r * HID + (ch + 1) * 128 + c);
                }
            }

            int kg0 = ch * 128;
#pragma unroll
            for (int kk = kpar; kk < 16; kk += 2) {
                int kb = kk * 8;
                uint32_t a0 = As[(mstrip * 16 + gid) * ARL + kb + tig];
                uint32_t a1 = As[(mstrip * 16 + gid + 8) * ARL + kb + tig];
                uint32_t a2 = As[(mstrip * 16 + gid) * ARL + kb + tig + 4];
                uint32_t a3 = As[(mstrip * 16 + gid + 8) * ARL + kb + tig + 4];
#pragma unroll
                for (int nf = 0; nf < 4; nf++) {
                    uint32_t b0 = BsT[(nf * 8 + gid) * BRL + kg0 + kb + tig];
                    uint32_t b1 = BsT[(nf * 8 + gid) * BRL + kg0 + kb + tig + 4];
                    mma_tf32(acc[nf], a0, a1, a2, a3, b0, b1);
                }
            }
            __syncthreads();
        }

        // K-split reduction: warps 4-7 -> smem, warps 0-3 accumulate
        if (wid >= 4) {
            float* rp = red + ((size_t)(wid - 4) * 32 + lane) * 16;
#pragma unroll
            for (int nf = 0; nf < 4; nf++)
                *(float4*)(rp + nf * 4) = *(const float4*)acc[nf];
        }
        __syncthreads();
        if (wid < 4) {
            float* rp = red + ((size_t)wid * 32 + lane) * 16;
#pragma unroll
            for (int nf = 0; nf < 4; nf++) {
                float4 v = *(const float4*)(rp + nf * 4);
                acc[nf][0] += v.x; acc[nf][1] += v.y;
                acc[nf][2] += v.z; acc[nf][3] += v.w;
            }

            // fused LSTM epilogue; c stays in registers
            float* h_out = out + (size_t)t * BATCH * HID;
#pragma unroll
            for (int rr = 0; rr < 2; rr++) {
#pragma unroll
                for (int cc = 0; cc < 2; cc++) {
                    int ci = rr * 2 + cc;
                    int r = r0 + rr * 8, col = hc + cc;
                    float iv = acc[0][ci] + xv[ci];
                    float fv = acc[1][ci] + xv[4 + ci];
                    float gv = acc[2][ci] + xv[8 + ci];
                    float ov = acc[3][ci] + xv[12 + ci];
                    iv = 1.f / (1.f + expf(-iv));
                    fv = 1.f / (1.f + expf(-fv));
                    gv = tanhf(gv);
                    ov = 1.f / (1.f + expf(-ov));
                    float cv = fv * creg[ci] + iv * gv;
                    creg[ci] = cv;
                    h_out[(size_t)r * HID + col] = ov * tanhf(cv);
                }
            }
        }

        // grid barrier: all h(t) visible before anyone reads it at t+1
        if (t + 1 < T_STEPS) {
            __syncthreads();
            if (tid == 0) {
                __threadfence();
                atomicAdd(&g_bar, 1u);
                unsigned tgt = (unsigned)(t + 1) * NCTA;
                while (ld_acq(&g_bar) < tgt) { }
            }
            __syncthreads();
        }
    }
}

// ---------------------------------------------------------------------------
extern "C" void kernel_launch(void* const* d_in, const int* in_sizes, int n_in,
                              void* d_out, int out_size) {
    const float* x  = (const float*)d_in[0];   // [T, B, D]
    const float* c0 = (const float*)d_in[1];   // [B, H]
    const float* h0 = (const float*)d_in[2];   // [B, H]
    const float* Wi = (const float*)d_in[3];   // [D, 4H]
    const float* Wh = (const float*)d_in[4];   // [H, 4H]
    const float* b  = (const float*)d_in[5];   // [4H]
    float* out = (float*)d_out;                // [T, B, H]

    cudaFuncSetAttribute(lstm_persist, cudaFuncAttributeMaxDynamicSharedMemorySize,
                         PERSIST_SMEM);

    // Reorder + tf32-round Wh; zero grid barrier
    wr_prep<<<(DIM * GATES) / 256, 256>>>(Wh);

    // Input projection (tf32 tensor cores)
    dim3 g1(GATES / 128, (T_STEPS * BATCH) / 128);
    xg_gemm_mma<<<g1, 256>>>(x, Wi, b);

    // Persistent recurrence: one launch for all 512 steps
    lstm_persist<<<NCTA, 256, PERSIST_SMEM>>>(h0, c0, out);
}

// round 5
// speedup vs baseline: 3.7792x; 1.0441x over previous
#include <cuda_runtime.h>
#include <math.h>
#include <stdint.h>

#define T_STEPS 512
#define BATCH   64
#define DIM     1024
#define HID     1024
#define GATES   4096
#define NCTA    128

// Scratch (__device__ globals: allocation-free rule)
__device__ float    g_xg[(size_t)T_STEPS * BATCH * GATES]; // x@Wi + b
__device__ uint32_t g_wr[(size_t)DIM * GATES];             // Wh reordered, tf32 bits, [k][col']
__device__ uint32_t g_ht[2][BATCH * HID];                  // h as tf32 bits, ping-pong
__device__ unsigned g_bar;                                 // grid barrier counter

// ---------------------------------------------------------------------------
// Helpers
// ---------------------------------------------------------------------------
__device__ __forceinline__ uint32_t f2tf(float v) {
    uint32_t u;
    asm("cvt.rna.tf32.f32 %0, %1;" : "=r"(u) : "f"(v));
    return u;
}

__device__ __forceinline__ void mma_tf32(float* c,
                                         uint32_t a0, uint32_t a1, uint32_t a2, uint32_t a3,
                                         uint32_t b0, uint32_t b1) {
    asm volatile(
        "mma.sync.aligned.m16n8k8.row.col.f32.tf32.tf32.f32 "
        "{%0,%1,%2,%3}, {%4,%5,%6,%7}, {%8,%9}, {%0,%1,%2,%3};"
        : "+f"(c[0]), "+f"(c[1]), "+f"(c[2]), "+f"(c[3])
        : "r"(a0), "r"(a1), "r"(a2), "r"(a3), "r"(b0), "r"(b1));
}

__device__ __forceinline__ unsigned ld_acq(const unsigned* p) {
    unsigned v;
    asm volatile("ld.acquire.gpu.global.u32 %0, [%1];" : "=r"(v) : "l"(p));
    return v;
}

__device__ __forceinline__ uint32_t smem_u32(const void* p) {
    uint32_t a;
    asm("{ .reg .u64 t; cvta.to.shared.u64 t, %1; cvt.u32.u64 %0, t; }" : "=r"(a) : "l"(p));
    return a;
}

#define CP_ASYNC16(dst, src) \
    asm volatile("cp.async.cg.shared.global [%0], [%1], 16;" :: "r"(dst), "l"(src))
#define CP_COMMIT() asm volatile("cp.async.commit_group;" ::: "memory")
#define CP_WAIT0()  asm volatile("cp.async.wait_group 0;" ::: "memory")

// ---------------------------------------------------------------------------
// Kernel 0: reorder Wh -> g_wr (tf32, gate-interleaved), h0 -> g_ht[0] (tf32),
// zero grid barrier.
// ---------------------------------------------------------------------------
__global__ __launch_bounds__(256) void wr_prep(const float* __restrict__ Wh,
                                               const float* __restrict__ h0) {
    int idx = blockIdx.x * 256 + threadIdx.x;   // k*4096 + col
    if (idx == 0) g_bar = 0;
    if (idx < BATCH * HID) g_ht[0][idx] = f2tf(h0[idx]);
    int col = idx & 4095;
    int k   = idx >> 12;
    int g = col >> 10, rem = col & 1023, c = rem >> 3, j = rem & 7;
    g_wr[(size_t)k * GATES + c * 32 + g * 8 + j] = f2tf(Wh[idx]);
}

// ---------------------------------------------------------------------------
// Kernel 1: xg = x @ Wi + b via tf32 mma.sync (unchanged, known-good).
// ---------------------------------------------------------------------------
__global__ __launch_bounds__(256) void xg_gemm_mma(const float* __restrict__ x,
                                                   const float* __restrict__ Wi,
                                                   const float* __restrict__ bias) {
    __shared__ uint32_t As[128][36];
    __shared__ uint32_t Bs[32][132];

    int tid = threadIdx.x, wid = tid >> 5, lane = tid & 31;
    int gid = lane >> 2, tig = lane & 3;
    int bm = blockIdx.y * 128, bn = blockIdx.x * 128;
    int wrow = (wid & 3) * 32, wcol = (wid >> 2) * 64;

    float acc[2][8][4];
#pragma unroll
    for (int i = 0; i < 2; i++)
#pragma unroll
        for (int j = 0; j < 8; j++)
#pragma unroll
            for (int k = 0; k < 4; k++) acc[i][j][k] = 0.f;

    float4 pa[4], pb[4];

#pragma unroll
    for (int u = 0; u < 4; u++) {
        int s = u * 256 + tid, r = s >> 3, c = (s & 7) * 4;
        pa[u] = *(const float4*)(x + (size_t)(bm + r) * DIM + c);
    }
#pragma unroll
    for (int u = 0; u < 4; u++) {
        int s = u * 256 + tid, r = s >> 5, c = (s & 31) * 4;
        pb[u] = *(const float4*)(Wi + (size_t)r * GATES + bn + c);
    }

    for (int k0 = 0; k0 < DIM; k0 += 32) {
#pragma unroll
        for (int u = 0; u < 4; u++) {
            int s = u * 256 + tid, r = s >> 3, c = (s & 7) * 4;
            As[r][c + 0] = f2tf(pa[u].x); As[r][c + 1] = f2tf(pa[u].y);
            As[r][c + 2] = f2tf(pa[u].z); As[r][c + 3] = f2tf(pa[u].w);
        }
#pragma unroll
        for (int u = 0; u < 4; u++) {
            int s = u * 256 + tid, r = s >> 5, c = (s & 31) * 4;
            Bs[r][c + 0] = f2tf(pb[u].x); Bs[r][c + 1] = f2tf(pb[u].y);
            Bs[r][c + 2] = f2tf(pb[u].z); Bs[r][c + 3] = f2tf(pb[u].w);
        }
        __syncthreads();

        if (k0 + 32 < DIM) {
#pragma unroll
            for (int u = 0; u < 4; u++) {
                int s = u * 256 + tid, r = s >> 3, c = (s & 7) * 4;
                pa[u] = *(const float4*)(x + (size_t)(bm + r) * DIM + k0 + 32 + c);
            }
#pragma unroll
            for (int u = 0; u < 4; u++) {
                int s = u * 256 + tid, r = s >> 5, c = (s & 31) * 4;
                pb[u] = *(const float4*)(Wi + (size_t)(k0 + 32 + r) * GATES + bn + c);
            }
        }

#pragma unroll
        for (int kk = 0; kk < 4; kk++) {
            int kb = kk * 8;
            uint32_t a[2][4];
#pragma unroll
            for (int mf = 0; mf < 2; mf++) {
                int m = wrow + mf * 16 + gid;
                a[mf][0] = As[m][kb + tig];
                a[mf][1] = As[m + 8][kb + tig];
                a[mf][2] = As[m][kb + tig + 4];
                a[mf][3] = As[m + 8][kb + tig + 4];
            }
#pragma unroll
            for (int nf = 0; nf < 8; nf++) {
                uint32_t b0 = Bs[kb + tig][wcol + nf * 8 + gid];
                uint32_t b1 = Bs[kb + tig + 4][wcol + nf * 8 + gid];
                mma_tf32(acc[0][nf], a[0][0], a[0][1], a[0][2], a[0][3], b0, b1);
                mma_tf32(acc[1][nf], a[1][0], a[1][1], a[1][2], a[1][3], b0, b1);
            }
        }
        __syncthreads();
    }

#pragma unroll
    for (int mf = 0; mf < 2; mf++)
#pragma unroll
        for (int nf = 0; nf < 8; nf++) {
            int row = bm + wrow + mf * 16 + gid;
            int col = bn + wcol + nf * 8 + 2 * tig;
            float bv0 = bias[col], bv1 = bias[col + 1];
            g_xg[(size_t)row * GATES + col]           = acc[mf][nf][0] + bv0;
            g_xg[(size_t)row * GATES + col + 1]       = acc[mf][nf][1] + bv1;
            g_xg[(size_t)(row + 8) * GATES + col]     = acc[mf][nf][2] + bv0;
            g_xg[(size_t)(row + 8) * GATES + col + 1] = acc[mf][nf][3] + bv1;
        }
}

// ---------------------------------------------------------------------------
// Kernel 2: persistent recurrence, cp.async-pipelined, 32x32 warp tiles with
// 4-way K-split. Warp w: mgrp = w&1 (rows mgrp*32..+32), ksp = w>>1
// (k8-groups kk % 4 == ksp). Owners (w 0,1) hold c-state + run epilogue.
// ---------------------------------------------------------------------------
#define BRL 1028                   // B row len (words), 1028 % 32 == 4
#define ARL 132                    // A row len (words), 132 % 32 == 4
#define BSZ (32 * BRL)             // 32896 words
#define ACH (64 * ARL)             // 8448 words per A buffer
#define RSL 36                     // reduce row stride (words), conflict-free
#define PERSIST_SMEM ((BSZ + 2 * ACH) * 4)   // 199168 bytes

__device__ __forceinline__ void stage_chunk(uint32_t dst_base,
                                            const uint32_t* __restrict__ hsrc,
                                            int ch, int tid) {
#pragma unroll
    for (int u = 0; u < 8; u++) {
        int idx = u * 256 + tid;
        int r = idx >> 5, c4 = (idx & 31) * 4;
        uint32_t dst = dst_base + (uint32_t)(r * ARL + c4) * 4;
        const uint32_t* src = hsrc + (size_t)r * HID + ch * 128 + c4;
        CP_ASYNC16(dst, src);
    }
    CP_COMMIT();
}

__global__ __launch_bounds__(256, 1) void lstm_persist(const float* __restrict__ c0,
                                                       float* __restrict__ out) {
    extern __shared__ uint32_t sm[];
    uint32_t* BsT = sm;            // [32][1028]
    uint32_t* Abuf = sm + BSZ;     // 2 x [64][132]
    float* red = (float*)(sm + BSZ);  // overlays A buffer 0 (safe at reduce time)

    uint32_t a0addr = smem_u32(Abuf);
    uint32_t a1addr = a0addr + ACH * 4;

    int tid = threadIdx.x, wid = tid >> 5, lane = tid & 31;
    int gid = lane >> 2, tig = lane & 3;
    int cta = blockIdx.x;
    int mgrp = wid & 1, ksp = wid >> 1;
    int n0 = cta * 32;

    // Load resident B slice: BsT[n][k] = g_wr[k][n0+n]
    for (int s = tid; s < 1024 * 8; s += 256) {
        int k = s >> 3, c4 = (s & 7) * 4;
        uint4 v = *(const uint4*)(g_wr + (size_t)k * GATES + n0 + c4);
        BsT[(c4 + 0) * BRL + k] = v.x;
        BsT[(c4 + 1) * BRL + k] = v.y;
        BsT[(c4 + 2) * BRL + k] = v.z;
        BsT[(c4 + 3) * BRL + k] = v.w;
    }

    // Owner threads (warps 0,1): 8 cells = {mf 2} x {rr 2} x {cc 2}
    // row = wid*32 + mf*16 + gid + rr*8 ; col = cta*8 + tig*2 + cc
    float creg[8];
    float xv[32];   // [mf][gate][rr*2+cc]
    if (wid < 2) {
#pragma unroll
        for (int mf = 0; mf < 2; mf++)
#pragma unroll
            for (int rr = 0; rr < 2; rr++)
#pragma unroll
                for (int cc = 0; cc < 2; cc++) {
                    int row = wid * 32 + mf * 16 + gid + rr * 8;
                    int col = cta * 8 + tig * 2 + cc;
                    creg[mf * 4 + rr * 2 + cc] = c0[(size_t)row * HID + col];
                }
        // prefetch xg for t=0
#pragma unroll
        for (int mf = 0; mf < 2; mf++)
#pragma unroll
            for (int g = 0; g < 4; g++)
#pragma unroll
                for (int rr = 0; rr < 2; rr++)
#pragma unroll
                    for (int cc = 0; cc < 2; cc++) {
                        int row = wid * 32 + mf * 16 + gid + rr * 8;
                        int col = cta * 8 + tig * 2 + cc;
                        xv[mf * 16 + g * 4 + rr * 2 + cc] =
                            g_xg[(size_t)row * GATES + g * 1024 + col];
                    }
    }
    __syncthreads();

    for (int t = 0; t < T_STEPS; t++) {
        const uint32_t* hsrc = g_ht[t & 1];

        float acc[2][4][4];
#pragma unroll
        for (int i = 0; i < 2; i++)
#pragma unroll
            for (int j = 0; j < 4; j++)
#pragma unroll
                for (int k = 0; k < 4; k++) acc[i][j][k] = 0.f;

        stage_chunk(a0addr, hsrc, 0, tid);

        for (int ch = 0; ch < 8; ch++) {
            CP_WAIT0();
            __syncthreads();
            if (ch < 7)
                stage_chunk((ch & 1) ? a0addr : a1addr, hsrc, ch + 1, tid);

            const uint32_t* A = Abuf + ((ch & 1) ? ACH : 0);
            int kgch = ch * 128;
#pragma unroll
            for (int kq = 0; kq < 4; kq++) {
                int kb = (kq * 4 + ksp) * 8;
                uint32_t a[2][4];
#pragma unroll
                for (int mf = 0; mf < 2; mf++) {
                    int base = (mgrp * 32 + mf * 16 + gid) * ARL + kb + tig;
                    a[mf][0] = A[base];
                    a[mf][1] = A[base + 8 * ARL];
                    a[mf][2] = A[base + 4];
                    a[mf][3] = A[base + 8 * ARL + 4];
                }
#pragma unroll
                for (int nf = 0; nf < 4; nf++) {
                    int bb = (nf * 8 + gid) * BRL + kgch + kb + tig;
                    uint32_t b0 = BsT[bb], b1 = BsT[bb + 4];
                    mma_tf32(acc[0][nf], a[0][0], a[0][1], a[0][2], a[0][3], b0, b1);
                    mma_tf32(acc[1][nf], a[1][0], a[1][1], a[1][2], a[1][3], b0, b1);
                }
            }
        }
        __syncthreads();   // all MMAs done; A buffer 0 reusable as reduce space

        // 4-way K-split reduction (warps 2-7 -> red, owners accumulate)
        if (ksp > 0) {
            float* rp = red + (size_t)(((ksp - 1) * 2 + mgrp) * 32 + lane) * RSL;
#pragma unroll
            for (int mf = 0; mf < 2; mf++)
#pragma unroll
                for (int nf = 0; nf < 4; nf++)
                    *(float4*)(rp + (mf * 4 + nf) * 4) = *(const float4*)acc[mf][nf];
        }
        __syncthreads();

        if (wid < 2) {
#pragma unroll
            for (int s = 0; s < 3; s++) {
                const float* rp = red + (size_t)((s * 2 + mgrp) * 32 + lane) * RSL;
#pragma unroll
                for (int mf = 0; mf < 2; mf++)
#pragma unroll
                    for (int nf = 0; nf < 4; nf++) {
                        float4 v = *(const float4*)(rp + (mf * 4 + nf) * 4);
                        acc[mf][nf][0] += v.x; acc[mf][nf][1] += v.y;
                        acc[mf][nf][2] += v.z; acc[mf][nf][3] += v.w;
                    }
            }

            // fused LSTM epilogue; write h as fp32 (out) + tf32 (g_ht ping-pong)
            float* h_out = out + (size_t)t * BATCH * HID;
            uint32_t* hnext = g_ht[(t + 1) & 1];
#pragma unroll
            for (int mf = 0; mf < 2; mf++)
#pragma unroll
                for (int rr = 0; rr < 2; rr++)
#pragma unroll
                    for (int cc = 0; cc < 2; cc++) {
                        int ci = rr * 2 + cc;
                        int cell = mf * 4 + ci;
                        int row = wid * 32 + mf * 16 + gid + rr * 8;
                        int col = cta * 8 + tig * 2 + cc;
                        float iv = acc[mf][0][ci] + xv[mf * 16 + ci];
                        float fv = acc[mf][1][ci] + xv[mf * 16 + 4 + ci];
                        float gv = acc[mf][2][ci] + xv[mf * 16 + 8 + ci];
                        float ov = acc[mf][3][ci] + xv[mf * 16 + 12 + ci];
                        iv = 1.f / (1.f + expf(-iv));
                        fv = 1.f / (1.f + expf(-fv));
                        gv = tanhf(gv);
                        ov = 1.f / (1.f + expf(-ov));
                        float cv = fv * creg[cell] + iv * gv;
                        creg[cell] = cv;
                        float hv = ov * tanhf(cv);
                        h_out[(size_t)row * HID + col] = hv;
                        hnext[(size_t)row * HID + col] = f2tf(hv);
                    }
        }

        if (t + 1 < T_STEPS) {
            __syncthreads();                  // epilogue stores ordered before release
            if (tid == 0) {
                __threadfence();
                atomicAdd(&g_bar, 1u);
            }
            // overlap barrier wait with xg prefetch for t+1
            if (wid < 2) {
                const float* xg_n = g_xg + (size_t)(t + 1) * BATCH * GATES;
#pragma unroll
                for (int mf = 0; mf < 2; mf++)
#pragma unroll
                    for (int g = 0; g < 4; g++)
#pragma unroll
                        for (int rr = 0; rr < 2; rr++)
#pragma unroll
                            for (int cc = 0; cc < 2; cc++) {
                                int row = wid * 32 + mf * 16 + gid + rr * 8;
                                int col = cta * 8 + tig * 2 + cc;
                                xv[mf * 16 + g * 4 + rr * 2 + cc] =
                                    xg_n[(size_t)row * GATES + g * 1024 + col];
                            }
            }
            if (tid == 0) {
                unsigned tgt = (unsigned)(t + 1) * NCTA;
                while (ld_acq(&g_bar) < tgt) { }
            }
            __syncthreads();
        }
    }
}

// ---------------------------------------------------------------------------
extern "C" void kernel_launch(void* const* d_in, const int* in_sizes, int n_in,
                              void* d_out, int out_size) {
    const float* x  = (const float*)d_in[0];   // [T, B, D]
    const float* c0 = (const float*)d_in[1];   // [B, H]
    const float* h0 = (const float*)d_in[2];   // [B, H]
    const float* Wi = (const float*)d_in[3];   // [D, 4H]
    const float* Wh = (const float*)d_in[4];   // [H, 4H]
    const float* b  = (const float*)d_in[5];   // [4H]
    float* out = (float*)d_out;                // [T, B, H]

    cudaFuncSetAttribute(lstm_persist, cudaFuncAttributeMaxDynamicSharedMemorySize,
                         PERSIST_SMEM);

    // Reorder/round Wh, convert h0, zero barrier
    wr_prep<<<(DIM * GATES) / 256, 256>>>(Wh, h0);

    // Input projection (tf32 tensor cores)
    dim3 g1(GATES / 128, (T_STEPS * BATCH) / 128);
    xg_gemm_mma<<<g1, 256>>>(x, Wi, b);

    // Persistent recurrence: one launch, all 512 steps
    lstm_persist<<<NCTA, 256, PERSIST_SMEM>>>(c0, out);
}

// round 6
// speedup vs baseline: 3.9285x; 1.0395x over previous
#include <cuda_runtime.h>
#include <math.h>
#include <stdint.h>

#define T_STEPS 512
#define BATCH   64
#define DIM     1024
#define HID     1024
#define GATES   4096
#define NCTA    128

// Scratch (__device__ globals: allocation-free rule)
__device__ float    g_xg[(size_t)T_STEPS * BATCH * GATES]; // x@Wi + b
__device__ uint32_t g_wrT[(size_t)GATES * DIM];            // Wh reordered [n'][k], tf32 bits
__device__ uint32_t g_ht[2][BATCH * HID];                  // h as tf32 bits, ping-pong
__device__ unsigned g_flags[NCTA];                         // barrier flags (one per CTA)

// ---------------------------------------------------------------------------
// Helpers
// ---------------------------------------------------------------------------
__device__ __forceinline__ uint32_t f2tf(float v) {
    uint32_t u;
    asm("cvt.rna.tf32.f32 %0, %1;" : "=r"(u) : "f"(v));
    return u;
}

__device__ __forceinline__ void mma_tf32(float* c,
                                         uint32_t a0, uint32_t a1, uint32_t a2, uint32_t a3,
                                         uint32_t b0, uint32_t b1) {
    asm volatile(
        "mma.sync.aligned.m16n8k8.row.col.f32.tf32.tf32.f32 "
        "{%0,%1,%2,%3}, {%4,%5,%6,%7}, {%8,%9}, {%0,%1,%2,%3};"
        : "+f"(c[0]), "+f"(c[1]), "+f"(c[2]), "+f"(c[3])
        : "r"(a0), "r"(a1), "r"(a2), "r"(a3), "r"(b0), "r"(b1));
}

__device__ __forceinline__ unsigned ld_acq(const unsigned* p) {
    unsigned v;
    asm volatile("ld.acquire.gpu.global.u32 %0, [%1];" : "=r"(v) : "l"(p));
    return v;
}
__device__ __forceinline__ void st_rlx(unsigned* p, unsigned v) {
    asm volatile("st.relaxed.gpu.global.u32 [%0], %1;" :: "l"(p), "r"(v) : "memory");
}

__device__ __forceinline__ uint32_t smem_u32(const void* p) {
    uint32_t a;
    asm("{ .reg .u64 t; cvta.to.shared.u64 t, %1; cvt.u32.u64 %0, t; }" : "=r"(a) : "l"(p));
    return a;
}

#define CP_ASYNC16(dst, src) \
    asm volatile("cp.async.cg.shared.global [%0], [%1], 16;" :: "r"(dst), "l"(src))
#define CP_COMMIT() asm volatile("cp.async.commit_group;" ::: "memory")
#define CP_WAIT0()  asm volatile("cp.async.wait_group 0;" ::: "memory")
#define CP_WAIT1()  asm volatile("cp.async.wait_group 1;" ::: "memory")

#define LDSM4(r0, r1, r2, r3, addr) \
    asm volatile("ldmatrix.sync.aligned.m8n8.x4.shared.b16 {%0,%1,%2,%3}, [%4];" \
                 : "=r"(r0), "=r"(r1), "=r"(r2), "=r"(r3) : "r"(addr))

// ---------------------------------------------------------------------------
// Kernel 1: xg = x @ Wi + b via tf32 mma.sync. ALSO (fused pre-work):
// reorder Wh -> g_wrT, convert h0 -> g_ht[0], reset g_flags.
// ---------------------------------------------------------------------------
__global__ __launch_bounds__(256) void xg_gemm_mma(const float* __restrict__ x,
                                                   const float* __restrict__ Wi,
                                                   const float* __restrict__ bias,
                                                   const float* __restrict__ Wh,
                                                   const float* __restrict__ h0) {
    // ---- fused prep (2M threads, 2 Wh elements each) ----
    {
        int gtid = (blockIdx.y * gridDim.x + blockIdx.x) * 256 + threadIdx.x;
        if (gtid < NCTA) g_flags[gtid] = 0;
        if (gtid < BATCH * HID) g_ht[0][gtid] = f2tf(h0[gtid]);
#pragma unroll
        for (int e = 0; e < 2; e++) {
            int idx = e * (DIM * GATES / 2) + gtid;
            int col = idx & 4095, k = idx >> 12;
            int g = col >> 10, rem = col & 1023, c = rem >> 3, j = rem & 7;
            int np = c * 32 + g * 8 + j;
            g_wrT[(size_t)np * DIM + k] = f2tf(Wh[idx]);
        }
    }

    __shared__ uint32_t As[128][36];
    __shared__ uint32_t Bs[32][132];

    int tid = threadIdx.x, wid = tid >> 5, lane = tid & 31;
    int gid = lane >> 2, tig = lane & 3;
    int bm = blockIdx.y * 128, bn = blockIdx.x * 128;
    int wrow = (wid & 3) * 32, wcol = (wid >> 2) * 64;

    float acc[2][8][4];
#pragma unroll
    for (int i = 0; i < 2; i++)
#pragma unroll
        for (int j = 0; j < 8; j++)
#pragma unroll
            for (int k = 0; k < 4; k++) acc[i][j][k] = 0.f;

    float4 pa[4], pb[4];

#pragma unroll
    for (int u = 0; u < 4; u++) {
        int s = u * 256 + tid, r = s >> 3, c = (s & 7) * 4;
        pa[u] = *(const float4*)(x + (size_t)(bm + r) * DIM + c);
    }
#pragma unroll
    for (int u = 0; u < 4; u++) {
        int s = u * 256 + tid, r = s >> 5, c = (s & 31) * 4;
        pb[u] = *(const float4*)(Wi + (size_t)r * GATES + bn + c);
    }

    for (int k0 = 0; k0 < DIM; k0 += 32) {
#pragma unroll
        for (int u = 0; u < 4; u++) {
            int s = u * 256 + tid, r = s >> 3, c = (s & 7) * 4;
            As[r][c + 0] = f2tf(pa[u].x); As[r][c + 1] = f2tf(pa[u].y);
            As[r][c + 2] = f2tf(pa[u].z); As[r][c + 3] = f2tf(pa[u].w);
        }
#pragma unroll
        for (int u = 0; u < 4; u++) {
            int s = u * 256 + tid, r = s >> 5, c = (s & 31) * 4;
            Bs[r][c + 0] = f2tf(pb[u].x); Bs[r][c + 1] = f2tf(pb[u].y);
            Bs[r][c + 2] = f2tf(pb[u].z); Bs[r][c + 3] = f2tf(pb[u].w);
        }
        __syncthreads();

        if (k0 + 32 < DIM) {
#pragma unroll
            for (int u = 0; u < 4; u++) {
                int s = u * 256 + tid, r = s >> 3, c = (s & 7) * 4;
                pa[u] = *(const float4*)(x + (size_t)(bm + r) * DIM + k0 + 32 + c);
            }
#pragma unroll
            for (int u = 0; u < 4; u++) {
                int s = u * 256 + tid, r = s >> 5, c = (s & 31) * 4;
                pb[u] = *(const float4*)(Wi + (size_t)(k0 + 32 + r) * GATES + bn + c);
            }
        }

#pragma unroll
        for (int kk = 0; kk < 4; kk++) {
            int kb = kk * 8;
            uint32_t a[2][4];
#pragma unroll
            for (int mf = 0; mf < 2; mf++) {
                int m = wrow + mf * 16 + gid;
                a[mf][0] = As[m][kb + tig];
                a[mf][1] = As[m + 8][kb + tig];
                a[mf][2] = As[m][kb + tig + 4];
                a[mf][3] = As[m + 8][kb + tig + 4];
            }
#pragma unroll
            for (int nf = 0; nf < 8; nf++) {
                uint32_t b0 = Bs[kb + tig][wcol + nf * 8 + gid];
                uint32_t b1 = Bs[kb + tig + 4][wcol + nf * 8 + gid];
                mma_tf32(acc[0][nf], a[0][0], a[0][1], a[0][2], a[0][3], b0, b1);
                mma_tf32(acc[1][nf], a[1][0], a[1][1], a[1][2], a[1][3], b0, b1);
            }
        }
        __syncthreads();
    }

#pragma unroll
    for (int mf = 0; mf < 2; mf++)
#pragma unroll
        for (int nf = 0; nf < 8; nf++) {
            int row = bm + wrow + mf * 16 + gid;
            int col = bn + wcol + nf * 8 + 2 * tig;
            float bv0 = bias[col], bv1 = bias[col + 1];
            g_xg[(size_t)row * GATES + col]           = acc[mf][nf][0] + bv0;
            g_xg[(size_t)row * GATES + col + 1]       = acc[mf][nf][1] + bv1;
            g_xg[(size_t)(row + 8) * GATES + col]     = acc[mf][nf][2] + bv0;
            g_xg[(size_t)(row + 8) * GATES + col + 1] = acc[mf][nf][3] + bv1;
        }
}

// ---------------------------------------------------------------------------
// Kernel 2: persistent recurrence. XOR-swizzled smem, ldmatrix fragments,
// 3-deep cp.async pipeline, flag-array barrier with poll/epilogue overlap.
// Warp w: mgrp = w&1 (rows mgrp*32..+32), ksp = w>>1 (k8 groups kk%4==ksp).
// Owners: warps 0-3; warp ow owns cells (mgrp=ow&1, mf=ow>>1).
// ---------------------------------------------------------------------------
#define BBYTES 131072                 // B: 32 rows x 4096 B (XOR swizzle, no pad)
#define ABYTES 32768                  // A chunk: 64 rows x 512 B
#define PERSIST_SMEM (BBYTES + 3 * ABYTES)   // 229376 <= 232448

__device__ __forceinline__ void stage_chunk(uint32_t dstbase,
                                            const uint32_t* __restrict__ hsrc,
                                            int ch, int tid) {
#pragma unroll
    for (int u = 0; u < 8; u++) {
        int idx = u * 256 + tid;
        int r = idx >> 5;              // 0..63
        int seg = idx & 31;            // 16-B segment in row
        uint32_t dst = dstbase + (uint32_t)(r * 512 + ((seg * 16) ^ ((r & 7) * 16)));
        const uint32_t* src = hsrc + (size_t)r * HID + ch * 128 + seg * 4;
        CP_ASYNC16(dst, src);
    }
    CP_COMMIT();
}

__global__ __launch_bounds__(256, 1) void lstm_persist(const float* __restrict__ c0,
                                                       float* __restrict__ out) {
    extern __shared__ uint32_t sm[];
    char* smc = (char*)sm;
    uint32_t sbase = smem_u32(sm);

    int tid = threadIdx.x, wid = tid >> 5, lane = tid & 31;
    int gid = lane >> 2, tig = lane & 3;
    int cta = blockIdx.x;
    int mgrp = wid & 1, ksp = wid >> 1;
    int n0 = cta * 32;

    // ---- stationary B fill: BsT[n][k] = g_wrT[n0+n][k], XOR swizzled ----
#pragma unroll 4
    for (int u = 0; u < 32; u++) {
        int idx = u * 256 + tid;
        int n = idx >> 8, seg = idx & 255;
        uint4 v = *(const uint4*)(g_wrT + (size_t)(n0 + n) * DIM + seg * 4);
        *(uint4*)(smc + n * 4096 + ((seg * 16) ^ ((n & 7) * 16))) = v;
    }

    // ---- ldmatrix lane addressing constants ----
    int tl = lane >> 3, ri = lane & 7;
    uint32_t aHalf = (uint32_t)((tl >> 1) * 16);
    int arow0 = mgrp * 32 + (tl & 1) * 8 + ri;
    int arow1 = arow0 + 16;
    uint32_t aOff0 = (uint32_t)arow0 * 512, aSw0 = (uint32_t)((arow0 & 7) * 16);
    uint32_t aOff1 = (uint32_t)arow1 * 512, aSw1 = (uint32_t)((arow1 & 7) * 16);
    uint32_t bHalf = (uint32_t)((tl & 1) * 16);
    int brow0 = (tl >> 1) * 8 + ri;
    int brow1 = brow0 + 16;
    uint32_t bOff0 = (uint32_t)brow0 * 4096, bSw0 = (uint32_t)((brow0 & 7) * 16);
    uint32_t bOff1 = (uint32_t)brow1 * 4096, bSw1 = (uint32_t)((brow1 & 7) * 16);
    uint32_t Abase = sbase + BBYTES;
    float* red = (float*)(smc + BBYTES);   // overlays A buffers at reduce time

    // ---- owner state: warp ow owns (mgrp=ow&1, mf=ow>>1) ----
    float creg[4];
    float xv[16];
    int orow0 = 0, ocol = 0;
    if (wid < 4) {
        int mg = wid & 1, mf = wid >> 1;
        orow0 = mg * 32 + mf * 16 + gid;          // + rr*8
        ocol = cta * 8 + tig * 2;                 // + cc
#pragma unroll
        for (int rr = 0; rr < 2; rr++)
#pragma unroll
            for (int cc = 0; cc < 2; cc++)
                creg[rr * 2 + cc] = c0[(size_t)(orow0 + rr * 8) * HID + ocol + cc];
#pragma unroll
        for (int g = 0; g < 4; g++)
#pragma unroll
            for (int rr = 0; rr < 2; rr++)
#pragma unroll
                for (int cc = 0; cc < 2; cc++)
                    xv[g * 4 + rr * 2 + cc] =
                        g_xg[(size_t)(orow0 + rr * 8) * GATES + g * 1024 + ocol + cc];
    }
    __syncthreads();

    for (int t = 0; t < T_STEPS; t++) {
        const uint32_t* hsrc = g_ht[t & 1];

        float acc[2][4][4];
#pragma unroll
        for (int i = 0; i < 2; i++)
#pragma unroll
            for (int j = 0; j < 4; j++)
#pragma unroll
                for (int k = 0; k < 4; k++) acc[i][j][k] = 0.f;

        stage_chunk(Abase, hsrc, 0, tid);
        stage_chunk(Abase + ABYTES, hsrc, 1, tid);

        for (int ch = 0; ch < 8; ch++) {
            if (ch == 7) { CP_WAIT0(); } else { CP_WAIT1(); }
            __syncthreads();
            if (ch < 6) {
                int nb = (ch + 2) % 3;
                stage_chunk(Abase + nb * ABYTES, hsrc, ch + 2, tid);
            }
            uint32_t Ab = Abase + (uint32_t)((ch % 3) * ABYTES);
            uint32_t chB = (uint32_t)(ch * 512);
#pragma unroll
            for (int kq = 0; kq < 4; kq++) {
                uint32_t kA = (uint32_t)(kq * 128 + ksp * 32);
                uint32_t a0[4], a1[4], bq[8];
                LDSM4(a0[0], a0[1], a0[2], a0[3], Ab + aOff0 + ((kA + aHalf) ^ aSw0));
                LDSM4(a1[0], a1[1], a1[2], a1[3], Ab + aOff1 + ((kA + aHalf) ^ aSw1));
                uint32_t kB = chB + kA;
                LDSM4(bq[0], bq[1], bq[2], bq[3], sbase + bOff0 + ((kB + bHalf) ^ bSw0));
                LDSM4(bq[4], bq[5], bq[6], bq[7], sbase + bOff1 + ((kB + bHalf) ^ bSw1));
                mma_tf32(acc[0][0], a0[0], a0[1], a0[2], a0[3], bq[0], bq[1]);
                mma_tf32(acc[0][1], a0[0], a0[1], a0[2], a0[3], bq[2], bq[3]);
                mma_tf32(acc[0][2], a0[0], a0[1], a0[2], a0[3], bq[4], bq[5]);
                mma_tf32(acc[0][3], a0[0], a0[1], a0[2], a0[3], bq[6], bq[7]);
                mma_tf32(acc[1][0], a1[0], a1[1], a1[2], a1[3], bq[0], bq[1]);
                mma_tf32(acc[1][1], a1[0], a1[1], a1[2], a1[3], bq[2], bq[3]);
                mma_tf32(acc[1][2], a1[0], a1[1], a1[2], a1[3], bq[4], bq[5]);
                mma_tf32(acc[1][3], a1[0], a1[1], a1[2], a1[3], bq[6], bq[7]);
            }
        }
        __syncthreads();   // MMAs done; A region reusable as reduce buffer

        // ---- all warps store partials ----
        {
            float* rp = red + (size_t)(wid * 32 + lane) * 36;
#pragma unroll
            for (int mf = 0; mf < 2; mf++)
#pragma unroll
                for (int nf = 0; nf < 4; nf++)
                    *(float4*)(rp + (mf * 16 + nf * 4)) = *(const float4*)acc[mf][nf];
        }
        __syncthreads();

        if (wid < 4) {
            int mg = wid & 1, mf = wid >> 1;
            // sum 4 K-split partials (ksp order 0..3 = previous summation order)
            float s[4][4];
#pragma unroll
            for (int nf = 0; nf < 4; nf++)
#pragma unroll
                for (int k = 0; k < 4; k++) s[nf][k] = 0.f;
#pragma unroll
            for (int sp = 0; sp < 4; sp++) {
                const float* rp = red + (size_t)((sp * 2 + mg) * 32 + lane) * 36 + mf * 16;
#pragma unroll
                for (int nf = 0; nf < 4; nf++) {
                    float4 v = *(const float4*)(rp + nf * 4);
                    s[nf][0] += v.x; s[nf][1] += v.y; s[nf][2] += v.z; s[nf][3] += v.w;
                }
            }

            // fused LSTM epilogue (c in regs); store tf32 h first (release path)
            uint32_t* hnext = g_ht[(t + 1) & 1];
            float hv[4];
#pragma unroll
            for (int rr = 0; rr < 2; rr++)
#pragma unroll
                for (int cc = 0; cc < 2; cc++) {
                    int ci = rr * 2 + cc;
                    float iv = s[0][ci] + xv[ci];
                    float fv = s[1][ci] + xv[4 + ci];
                    float gv = s[2][ci] + xv[8 + ci];
                    float ov = s[3][ci] + xv[12 + ci];
                    iv = 1.f / (1.f + expf(-iv));
                    fv = 1.f / (1.f + expf(-fv));
                    gv = tanhf(gv);
                    ov = 1.f / (1.f + expf(-ov));
                    float cv = fv * creg[ci] + iv * gv;
                    creg[ci] = cv;
                    float h = ov * tanhf(cv);
                    hv[ci] = h;
                    hnext[(size_t)(orow0 + rr * 8) * HID + ocol + cc] = f2tf(h);
                }

            // owner-warps barrier, then release this CTA's flag
            asm volatile("bar.sync 1, 128;" ::: "memory");
            if (tid == 0 && t + 1 < T_STEPS) {
                __threadfence();
                st_rlx(&g_flags[cta], (unsigned)(t + 1));
            }

            // fp32 output stores + next-step xg prefetch (off the fence path)
            float* h_out = out + (size_t)t * BATCH * HID;
#pragma unroll
            for (int rr = 0; rr < 2; rr++)
#pragma unroll
                for (int cc = 0; cc < 2; cc++)
                    h_out[(size_t)(orow0 + rr * 8) * HID + ocol + cc] = hv[rr * 2 + cc];

            if (t + 1 < T_STEPS) {
                const float* xg_n = g_xg + (size_t)(t + 1) * BATCH * GATES;
#pragma unroll
                for (int g = 0; g < 4; g++)
#pragma unroll
                    for (int rr = 0; rr < 2; rr++)
#pragma unroll
                        for (int cc = 0; cc < 2; cc++)
                            xv[g * 4 + rr * 2 + cc] =
                                xg_n[(size_t)(orow0 + rr * 8) * GATES + g * 1024 + ocol + cc];
            }
        } else {
            // poller warps: each thread watches one CTA's flag (overlaps epilogue)
            if (t + 1 < T_STEPS) {
                unsigned tgt = (unsigned)(t + 1);
                const unsigned* fp = &g_flags[tid - 128];
                while (ld_acq(fp) < tgt) { }
            }
        }
        __syncthreads();   // all flags observed -> safe to stage h(t+1)
    }
}

// ---------------------------------------------------------------------------
extern "C" void kernel_launch(void* const* d_in, const int* in_sizes, int n_in,
                              void* d_out, int out_size) {
    const float* x  = (const float*)d_in[0];   // [T, B, D]
    const float* c0 = (const float*)d_in[1];   // [B, H]
    const float* h0 = (const float*)d_in[2];   // [B, H]
    const float* Wi = (const float*)d_in[3];   // [D, 4H]
    const float* Wh = (const float*)d_in[4];   // [H, 4H]
    const float* b  = (const float*)d_in[5];   // [4H]
    float* out = (float*)d_out;                // [T, B, H]

    cudaFuncSetAttribute(lstm_persist, cudaFuncAttributeMaxDynamicSharedMemorySize,
                         PERSIST_SMEM);

    // Input projection + fused prep (Wh reorder, h0 cvt, flag reset)
    dim3 g1(GATES / 128, (T_STEPS * BATCH) / 128);
    xg_gemm_mma<<<g1, 256>>>(x, Wi, b, Wh, h0);

    // Persistent recurrence: one launch, all 512 steps
    lstm_persist<<<NCTA, 256, PERSIST_SMEM>>>(c0, out);
}

// round 7
// speedup vs baseline: 4.7426x; 1.2072x over previous
#include <cuda_runtime.h>
#include <cuda_fp16.h>
#include <math.h>
#include <stdint.h>

#define T_STEPS 512
#define BATCH   64
#define DIM     1024
#define HID     1024
#define GATES   4096
#define NCTA    128

// Scratch (__device__ globals: allocation-free rule)
__device__ float   g_xg[(size_t)T_STEPS * BATCH * GATES]; // x@Wi + b
__device__ __half  g_wrh[(size_t)GATES * DIM];            // Wh reordered [n'][k], fp16
__device__ __half  g_ht[2][BATCH * HID];                  // h as fp16, ping-pong
__device__ unsigned g_flags[NCTA];                        // barrier flags (one per CTA)

// ---------------------------------------------------------------------------
// Helpers
// ---------------------------------------------------------------------------
__device__ __forceinline__ uint32_t f2tf(float v) {
    uint32_t u;
    asm("cvt.rna.tf32.f32 %0, %1;" : "=r"(u) : "f"(v));
    return u;
}

// tf32 mma (xg gemm)
__device__ __forceinline__ void mma_tf32(float* c,
                                         uint32_t a0, uint32_t a1, uint32_t a2, uint32_t a3,
                                         uint32_t b0, uint32_t b1) {
    asm volatile(
        "mma.sync.aligned.m16n8k8.row.col.f32.tf32.tf32.f32 "
        "{%0,%1,%2,%3}, {%4,%5,%6,%7}, {%8,%9}, {%0,%1,%2,%3};"
        : "+f"(c[0]), "+f"(c[1]), "+f"(c[2]), "+f"(c[3])
        : "r"(a0), "r"(a1), "r"(a2), "r"(a3), "r"(b0), "r"(b1));
}

// fp16 mma (recurrence): D(16x8) += A(16x16) * B(16x8)
__device__ __forceinline__ void mma_f16(float* c,
                                        uint32_t a0, uint32_t a1, uint32_t a2, uint32_t a3,
                                        uint32_t b0, uint32_t b1) {
    asm volatile(
        "mma.sync.aligned.m16n8k16.row.col.f32.f16.f16.f32 "
        "{%0,%1,%2,%3}, {%4,%5,%6,%7}, {%8,%9}, {%0,%1,%2,%3};"
        : "+f"(c[0]), "+f"(c[1]), "+f"(c[2]), "+f"(c[3])
        : "r"(a0), "r"(a1), "r"(a2), "r"(a3), "r"(b0), "r"(b1));
}

__device__ __forceinline__ unsigned ld_acq(const unsigned* p) {
    unsigned v;
    asm volatile("ld.acquire.gpu.global.u32 %0, [%1];" : "=r"(v) : "l"(p));
    return v;
}
__device__ __forceinline__ void st_rel(unsigned* p, unsigned v) {
    asm volatile("st.release.gpu.global.u32 [%0], %1;" :: "l"(p), "r"(v) : "memory");
}

__device__ __forceinline__ uint32_t smem_u32(const void* p) {
    uint32_t a;
    asm("{ .reg .u64 t; cvta.to.shared.u64 t, %1; cvt.u32.u64 %0, t; }" : "=r"(a) : "l"(p));
    return a;
}

__device__ __forceinline__ float fsig(float x) {
    return 1.f / (1.f + __expf(-x));
}
__device__ __forceinline__ float ftanh(float x) {
    float e = __expf(-2.f * fabsf(x));
    float r = (1.f - e) / (1.f + e);
    return x < 0.f ? -r : r;
}

#define CP_ASYNC16(dst, src) \
    asm volatile("cp.async.cg.shared.global [%0], [%1], 16;" :: "r"(dst), "l"(src))
#define CP_COMMIT() asm volatile("cp.async.commit_group;" ::: "memory")
#define CP_WAIT0()  asm volatile("cp.async.wait_group 0;" ::: "memory")
#define CP_WAIT1()  asm volatile("cp.async.wait_group 1;" ::: "memory")

#define LDSM4(r0, r1, r2, r3, addr) \
    asm volatile("ldmatrix.sync.aligned.m8n8.x4.shared.b16 {%0,%1,%2,%3}, [%4];" \
                 : "=r"(r0), "=r"(r1), "=r"(r2), "=r"(r3) : "r"(addr))

// ---------------------------------------------------------------------------
// Kernel 1: xg = x @ Wi + b (tf32, unchanged). Fused prep: Wh -> g_wrh (fp16,
// gate-interleaved), h0 -> g_ht[0] (fp16), reset g_flags.
// ---------------------------------------------------------------------------
__global__ __launch_bounds__(256) void xg_gemm_mma(const float* __restrict__ x,
                                                   const float* __restrict__ Wi,
                                                   const float* __restrict__ bias,
                                                   const float* __restrict__ Wh,
                                                   const float* __restrict__ h0) {
    {
        int gtid = (blockIdx.y * gridDim.x + blockIdx.x) * 256 + threadIdx.x;
        if (gtid < NCTA) g_flags[gtid] = 0;
        if (gtid < BATCH * HID) g_ht[0][gtid] = __float2half_rn(h0[gtid]);
#pragma unroll
        for (int e = 0; e < 2; e++) {
            int idx = e * (DIM * GATES / 2) + gtid;
            int col = idx & 4095, k = idx >> 12;
            int g = col >> 10, rem = col & 1023, c = rem >> 3, j = rem & 7;
            int np = c * 32 + g * 8 + j;
            g_wrh[(size_t)np * DIM + k] = __float2half_rn(Wh[idx]);
        }
    }

    __shared__ uint32_t As[128][36];
    __shared__ uint32_t Bs[32][132];

    int tid = threadIdx.x, wid = tid >> 5, lane = tid & 31;
    int gid = lane >> 2, tig = lane & 3;
    int bm = blockIdx.y * 128, bn = blockIdx.x * 128;
    int wrow = (wid & 3) * 32, wcol = (wid >> 2) * 64;

    float acc[2][8][4];
#pragma unroll
    for (int i = 0; i < 2; i++)
#pragma unroll
        for (int j = 0; j < 8; j++)
#pragma unroll
            for (int k = 0; k < 4; k++) acc[i][j][k] = 0.f;

    float4 pa[4], pb[4];

#pragma unroll
    for (int u = 0; u < 4; u++) {
        int s = u * 256 + tid, r = s >> 3, c = (s & 7) * 4;
        pa[u] = *(const float4*)(x + (size_t)(bm + r) * DIM + c);
    }
#pragma unroll
    for (int u = 0; u < 4; u++) {
        int s = u * 256 + tid, r = s >> 5, c = (s & 31) * 4;
        pb[u] = *(const float4*)(Wi + (size_t)r * GATES + bn + c);
    }

    for (int k0 = 0; k0 < DIM; k0 += 32) {
#pragma unroll
        for (int u = 0; u < 4; u++) {
            int s = u * 256 + tid, r = s >> 3, c = (s & 7) * 4;
            As[r][c + 0] = f2tf(pa[u].x); As[r][c + 1] = f2tf(pa[u].y);
            As[r][c + 2] = f2tf(pa[u].z); As[r][c + 3] = f2tf(pa[u].w);
        }
#pragma unroll
        for (int u = 0; u < 4; u++) {
            int s = u * 256 + tid, r = s >> 5, c = (s & 31) * 4;
            Bs[r][c + 0] = f2tf(pb[u].x); Bs[r][c + 1] = f2tf(pb[u].y);
            Bs[r][c + 2] = f2tf(pb[u].z); Bs[r][c + 3] = f2tf(pb[u].w);
        }
        __syncthreads();

        if (k0 + 32 < DIM) {
#pragma unroll
            for (int u = 0; u < 4; u++) {
                int s = u * 256 + tid, r = s >> 3, c = (s & 7) * 4;
                pa[u] = *(const float4*)(x + (size_t)(bm + r) * DIM + k0 + 32 + c);
            }
#pragma unroll
            for (int u = 0; u < 4; u++) {
                int s = u * 256 + tid, r = s >> 5, c = (s & 31) * 4;
                pb[u] = *(const float4*)(Wi + (size_t)(k0 + 32 + r) * GATES + bn + c);
            }
        }

#pragma unroll
        for (int kk = 0; kk < 4; kk++) {
            int kb = kk * 8;
            uint32_t a[2][4];
#pragma unroll
            for (int mf = 0; mf < 2; mf++) {
                int m = wrow + mf * 16 + gid;
                a[mf][0] = As[m][kb + tig];
                a[mf][1] = As[m + 8][kb + tig];
                a[mf][2] = As[m][kb + tig + 4];
                a[mf][3] = As[m + 8][kb + tig + 4];
            }
#pragma unroll
            for (int nf = 0; nf < 8; nf++) {
                uint32_t b0 = Bs[kb + tig][wcol + nf * 8 + gid];
                uint32_t b1 = Bs[kb + tig + 4][wcol + nf * 8 + gid];
                mma_tf32(acc[0][nf], a[0][0], a[0][1], a[0][2], a[0][3], b0, b1);
                mma_tf32(acc[1][nf], a[1][0], a[1][1], a[1][2], a[1][3], b0, b1);
            }
        }
        __syncthreads();
    }

#pragma unroll
    for (int mf = 0; mf < 2; mf++)
#pragma unroll
        for (int nf = 0; nf < 8; nf++) {
            int row = bm + wrow + mf * 16 + gid;
            int col = bn + wcol + nf * 8 + 2 * tig;
            float bv0 = bias[col], bv1 = bias[col + 1];
            g_xg[(size_t)row * GATES + col]           = acc[mf][nf][0] + bv0;
            g_xg[(size_t)row * GATES + col + 1]       = acc[mf][nf][1] + bv1;
            g_xg[(size_t)(row + 8) * GATES + col]     = acc[mf][nf][2] + bv0;
            g_xg[(size_t)(row + 8) * GATES + col + 1] = acc[mf][nf][3] + bv1;
        }
}

// ---------------------------------------------------------------------------
// Kernel 2: persistent fp16 recurrence. m16n8k16 mma, XOR-swizzled smem,
// 3-buffer cp.async pipeline (4 chunks of K=256), flag barrier (st.release).
// Warp w: mgrp = w&1 (rows mgrp*32..+32), ksp = w>>1 (k16-groups g%4==ksp).
// ---------------------------------------------------------------------------
#define BBYTES 65536                  // B: 32 n-rows x 2048 B (fp16, K=1024)
#define ABYTES 32768                  // A chunk: 64 rows x 512 B (K=256 fp16)
#define PERSIST_SMEM (BBYTES + 3 * ABYTES)   // 163840

__device__ __forceinline__ void stage_chunk(uint32_t dstbase,
                                            const __half* __restrict__ hsrc,
                                            int ch, int tid) {
#pragma unroll
    for (int u = 0; u < 8; u++) {
        int idx = u * 256 + tid;
        int r = idx >> 5, seg = idx & 31;
        uint32_t dst = dstbase + (uint32_t)(r * 512 + ((seg * 16) ^ ((r & 7) * 16)));
        const __half* src = hsrc + (size_t)r * HID + ch * 256 + seg * 8;
        CP_ASYNC16(dst, src);
    }
    CP_COMMIT();
}

__global__ __launch_bounds__(256, 1) void lstm_persist(const float* __restrict__ c0,
                                                       float* __restrict__ out) {
    extern __shared__ uint32_t sm[];
    char* smc = (char*)sm;
    uint32_t sbase = smem_u32(sm);

    int tid = threadIdx.x, wid = tid >> 5, lane = tid & 31;
    int gid = lane >> 2, tig = lane & 3;
    int cta = blockIdx.x;
    int mgrp = wid & 1, ksp = wid >> 1;
    int n0 = cta * 32;

    // ---- stationary B fill: BsT[n][k] fp16, XOR swizzled (2048 B rows) ----
#pragma unroll 4
    for (int u = 0; u < 16; u++) {
        int idx = u * 256 + tid;
        int n = idx >> 7, seg = idx & 127;
        uint4 v = *(const uint4*)((const char*)g_wrh + ((size_t)(n0 + n) * DIM + seg * 8) * 2);
        *(uint4*)(smc + n * 2048 + ((seg * 16) ^ ((n & 7) * 16))) = v;
    }

    // ---- ldmatrix lane addressing ----
    int tl = lane >> 3, ri = lane & 7;
    uint32_t khalf = (uint32_t)((tl >> 1) * 16);           // A k sub-seg
    int rowA0 = mgrp * 32 + (tl & 1) * 8 + ri;             // mf=0
    int rowA1 = rowA0 + 16;                                // mf=1
    uint32_t aOff0 = (uint32_t)rowA0 * 512, aSw0 = (uint32_t)((rowA0 & 7) * 16);
    uint32_t aOff1 = (uint32_t)rowA1 * 512, aSw1 = (uint32_t)((rowA1 & 7) * 16);
    int nrowB0 = ((lane >> 4) & 1) * 8 + ri;               // nf tiles 0-1
    int nrowB1 = nrowB0 + 16;                              // nf tiles 2-3
    uint32_t kbB = (uint32_t)(((lane >> 3) & 1) * 16);     // B k sub-seg
    uint32_t bOff0 = (uint32_t)nrowB0 * 2048, bSw0 = (uint32_t)((nrowB0 & 7) * 16);
    uint32_t bOff1 = (uint32_t)nrowB1 * 2048, bSw1 = (uint32_t)((nrowB1 & 7) * 16);
    uint32_t Abase = sbase + BBYTES;
    float* red = (float*)(smc + BBYTES);   // overlays A buffers at reduce time

    // ---- owner state: warp ow (0-3) owns (mgrp=ow&1, mf=ow>>1) ----
    float creg[4];
    float xv[16];
    int orow0 = 0, ocol = 0;
    if (wid < 4) {
        int mg = wid & 1, mf = wid >> 1;
        orow0 = mg * 32 + mf * 16 + gid;
        ocol = cta * 8 + tig * 2;
#pragma unroll
        for (int rr = 0; rr < 2; rr++)
#pragma unroll
            for (int cc = 0; cc < 2; cc++)
                creg[rr * 2 + cc] = c0[(size_t)(orow0 + rr * 8) * HID + ocol + cc];
#pragma unroll
        for (int g = 0; g < 4; g++)
#pragma unroll
            for (int rr = 0; rr < 2; rr++)
#pragma unroll
                for (int cc = 0; cc < 2; cc++)
                    xv[g * 4 + rr * 2 + cc] =
                        g_xg[(size_t)(orow0 + rr * 8) * GATES + g * 1024 + ocol + cc];
    }
    __syncthreads();

    for (int t = 0; t < T_STEPS; t++) {
        const __half* hsrc = g_ht[t & 1];

        float acc[2][4][4];
#pragma unroll
        for (int i = 0; i < 2; i++)
#pragma unroll
            for (int j = 0; j < 4; j++)
#pragma unroll
                for (int k = 0; k < 4; k++) acc[i][j][k] = 0.f;

        stage_chunk(Abase, hsrc, 0, tid);
        stage_chunk(Abase + ABYTES, hsrc, 1, tid);

        for (int ch = 0; ch < 4; ch++) {
            if (ch == 3) { CP_WAIT0(); } else { CP_WAIT1(); }
            __syncthreads();
            if (ch < 2)
                stage_chunk(Abase + (uint32_t)(((ch + 2) % 3) * ABYTES), hsrc, ch + 2, tid);

            uint32_t Ab = Abase + (uint32_t)((ch % 3) * ABYTES);
            uint32_t chB = (uint32_t)(ch * 512);
#pragma unroll
            for (int kq = 0; kq < 4; kq++) {
                uint32_t kbyte = (uint32_t)((kq * 4 + ksp) * 32);
                uint32_t a0[4], a1[4], bq[8];
                LDSM4(a0[0], a0[1], a0[2], a0[3], Ab + aOff0 + ((kbyte + khalf) ^ aSw0));
                LDSM4(a1[0], a1[1], a1[2], a1[3], Ab + aOff1 + ((kbyte + khalf) ^ aSw1));
                uint32_t kB = chB + kbyte + kbB;
                LDSM4(bq[0], bq[1], bq[2], bq[3], sbase + bOff0 + (kB ^ bSw0));
                LDSM4(bq[4], bq[5], bq[6], bq[7], sbase + bOff1 + (kB ^ bSw1));
                mma_f16(acc[0][0], a0[0], a0[1], a0[2], a0[3], bq[0], bq[1]);
                mma_f16(acc[0][1], a0[0], a0[1], a0[2], a0[3], bq[2], bq[3]);
                mma_f16(acc[0][2], a0[0], a0[1], a0[2], a0[3], bq[4], bq[5]);
                mma_f16(acc[0][3], a0[0], a0[1], a0[2], a0[3], bq[6], bq[7]);
                mma_f16(acc[1][0], a1[0], a1[1], a1[2], a1[3], bq[0], bq[1]);
                mma_f16(acc[1][1], a1[0], a1[1], a1[2], a1[3], bq[2], bq[3]);
                mma_f16(acc[1][2], a1[0], a1[1], a1[2], a1[3], bq[4], bq[5]);
                mma_f16(acc[1][3], a1[0], a1[1], a1[2], a1[3], bq[6], bq[7]);
            }
        }
        __syncthreads();   // MMAs done; A region reusable as reduce buffer

        // ---- all warps store partials ----
        {
            float* rp = red + (size_t)(wid * 32 + lane) * 36;
#pragma unroll
            for (int mf = 0; mf < 2; mf++)
#pragma unroll
                for (int nf = 0; nf < 4; nf++)
                    *(float4*)(rp + (mf * 16 + nf * 4)) = *(const float4*)acc[mf][nf];
        }
        __syncthreads();

        if (wid < 4) {
            int mg = wid & 1, mf = wid >> 1;
            float s[4][4];
#pragma unroll
            for (int nf = 0; nf < 4; nf++)
#pragma unroll
                for (int k = 0; k < 4; k++) s[nf][k] = 0.f;
#pragma unroll
            for (int sp = 0; sp < 4; sp++) {
                const float* rp = red + (size_t)((sp * 2 + mg) * 32 + lane) * 36 + mf * 16;
#pragma unroll
                for (int nf = 0; nf < 4; nf++) {
                    float4 v = *(const float4*)(rp + nf * 4);
                    s[nf][0] += v.x; s[nf][1] += v.y; s[nf][2] += v.z; s[nf][3] += v.w;
                }
            }

            // fused LSTM epilogue; fp16 h first (release path)
            __half* hnext = g_ht[(t + 1) & 1];
            float hv[4];
#pragma unroll
            for (int rr = 0; rr < 2; rr++)
#pragma unroll
                for (int cc = 0; cc < 2; cc++) {
                    int ci = rr * 2 + cc;
                    float iv = fsig(s[0][ci] + xv[ci]);
                    float fv = fsig(s[1][ci] + xv[4 + ci]);
                    float gv = ftanh(s[2][ci] + xv[8 + ci]);
                    float ov = fsig(s[3][ci] + xv[12 + ci]);
                    float cv = fv * creg[ci] + iv * gv;
                    creg[ci] = cv;
                    float h = ov * ftanh(cv);
                    hv[ci] = h;
                    hnext[(size_t)(orow0 + rr * 8) * HID + ocol + cc] = __float2half_rn(h);
                }

            asm volatile("bar.sync 1, 128;" ::: "memory");
            if (tid == 0 && t + 1 < T_STEPS)
                st_rel(&g_flags[cta], (unsigned)(t + 1));

            // fp32 output stores + next-step xg prefetch (off the release path)
            float* h_out = out + (size_t)t * BATCH * HID;
#pragma unroll
            for (int rr = 0; rr < 2; rr++)
#pragma unroll
                for (int cc = 0; cc < 2; cc++)
                    h_out[(size_t)(orow0 + rr * 8) * HID + ocol + cc] = hv[rr * 2 + cc];

            if (t + 1 < T_STEPS) {
                const float* xg_n = g_xg + (size_t)(t + 1) * BATCH * GATES;
#pragma unroll
                for (int g = 0; g < 4; g++)
#pragma unroll
                    for (int rr = 0; rr < 2; rr++)
#pragma unroll
                        for (int cc = 0; cc < 2; cc++)
                            xv[g * 4 + rr * 2 + cc] =
                                xg_n[(size_t)(orow0 + rr * 8) * GATES + g * 1024 + ocol + cc];
            }
        } else {
            // poller warps: one flag per thread, overlaps owners' epilogue
            if (t + 1 < T_STEPS) {
                unsigned tgt = (unsigned)(t + 1);
                const unsigned* fp = &g_flags[tid - 128];
                while (ld_acq(fp) < tgt) { }
            }
        }
        __syncthreads();   // all flags observed -> safe to stage h(t+1)
    }
}

// ---------------------------------------------------------------------------
extern "C" void kernel_launch(void* const* d_in, const int* in_sizes, int n_in,
                              void* d_out, int out_size) {
    const float* x  = (const float*)d_in[0];   // [T, B, D]
    const float* c0 = (const float*)d_in[1];   // [B, H]
    const float* h0 = (const float*)d_in[2];   // [B, H]
    const float* Wi = (const float*)d_in[3];   // [D, 4H]
    const float* Wh = (const float*)d_in[4];   // [H, 4H]
    const float* b  = (const float*)d_in[5];   // [4H]
    float* out = (float*)d_out;                // [T, B, H]

    cudaFuncSetAttribute(lstm_persist, cudaFuncAttributeMaxDynamicSharedMemorySize,
                         PERSIST_SMEM);

    // Input projection + fused prep (Wh->fp16 reorder, h0 cvt, flag reset)
    dim3 g1(GATES / 128, (T_STEPS * BATCH) / 128);
    xg_gemm_mma<<<g1, 256>>>(x, Wi, b, Wh, h0);

    // Persistent recurrence: one launch, all 512 steps
    lstm_persist<<<NCTA, 256, PERSIST_SMEM>>>(c0, out);
}

// round 9
// speedup vs baseline: 4.7668x; 1.0051x over previous
#include <cuda_runtime.h>
#include <cuda_fp16.h>
#include <math.h>
#include <stdint.h>

#define T_STEPS 512
#define BATCH   64
#define DIM     1024
#define HID     1024
#define GATES   4096
#define NCTA    128

// Scratch (__device__ globals: allocation-free rule)
__device__ float   g_xg[(size_t)T_STEPS * BATCH * GATES]; // x@Wi + b
__device__ __half  g_wrh[(size_t)GATES * DIM];            // Wh reordered [n'][k], fp16
__device__ __half  g_ht[2][BATCH * HID];                  // h as fp16, ping-pong
__device__ unsigned g_flags[NCTA * 64];                   // per-CTA flag, 256B stride

// ---------------------------------------------------------------------------
// Helpers
// ---------------------------------------------------------------------------
__device__ __forceinline__ uint32_t f2tf(float v) {
    uint32_t u;
    asm("cvt.rna.tf32.f32 %0, %1;" : "=r"(u) : "f"(v));
    return u;
}

__device__ __forceinline__ void mma_tf32(float* c,
                                         uint32_t a0, uint32_t a1, uint32_t a2, uint32_t a3,
                                         uint32_t b0, uint32_t b1) {
    asm volatile(
        "mma.sync.aligned.m16n8k8.row.col.f32.tf32.tf32.f32 "
        "{%0,%1,%2,%3}, {%4,%5,%6,%7}, {%8,%9}, {%0,%1,%2,%3};"
        : "+f"(c[0]), "+f"(c[1]), "+f"(c[2]), "+f"(c[3])
        : "r"(a0), "r"(a1), "r"(a2), "r"(a3), "r"(b0), "r"(b1));
}

__device__ __forceinline__ void mma_f16(float* c,
                                        uint32_t a0, uint32_t a1, uint32_t a2, uint32_t a3,
                                        uint32_t b0, uint32_t b1) {
    asm volatile(
        "mma.sync.aligned.m16n8k16.row.col.f32.f16.f16.f32 "
        "{%0,%1,%2,%3}, {%4,%5,%6,%7}, {%8,%9}, {%0,%1,%2,%3};"
        : "+f"(c[0]), "+f"(c[1]), "+f"(c[2]), "+f"(c[3])
        : "r"(a0), "r"(a1), "r"(a2), "r"(a3), "r"(b0), "r"(b1));
}

__device__ __forceinline__ unsigned ld_acq(const unsigned* p) {
    unsigned v;
    asm volatile("ld.acquire.gpu.global.u32 %0, [%1];" : "=r"(v) : "l"(p));
    return v;
}
__device__ __forceinline__ void st_rel(unsigned* p, unsigned v) {
    asm volatile("st.release.gpu.global.u32 [%0], %1;" :: "l"(p), "r"(v) : "memory");
}

__device__ __forceinline__ uint32_t smem_u32(const void* p) {
    uint32_t a;
    asm("{ .reg .u64 t; cvta.to.shared.u64 t, %1; cvt.u32.u64 %0, t; }" : "=r"(a) : "l"(p));
    return a;
}

__device__ __forceinline__ float fsig(float x) { return 1.f / (1.f + __expf(-x)); }
__device__ __forceinline__ float ftanh(float x) {
    float e = __expf(-2.f * fabsf(x));
    float r = (1.f - e) / (1.f + e);
    return x < 0.f ? -r : r;
}

#define LDSM4(r0, r1, r2, r3, addr) \
    asm volatile("ldmatrix.sync.aligned.m8n8.x4.shared.b16 {%0,%1,%2,%3}, [%4];" \
                 : "=r"(r0), "=r"(r1), "=r"(r2), "=r"(r3) : "r"(addr))

// ---------------------------------------------------------------------------
// Kernel 1: xg = x @ Wi + b (tf32). Fused prep: Wh -> g_wrh (fp16, reordered
// np = c*64 + nh*32 + g*8 + jj for col = g*1024 + c*16 + nh*8 + jj),
// h0 -> g_ht[0], reset flags.
// ---------------------------------------------------------------------------
__global__ __launch_bounds__(256) void xg_gemm_mma(const float* __restrict__ x,
                                                   const float* __restrict__ Wi,
                                                   const float* __restrict__ bias,
                                                   const float* __restrict__ Wh,
                                                   const float* __restrict__ h0) {
    {
        int gtid = (blockIdx.y * gridDim.x + blockIdx.x) * 256 + threadIdx.x;
        if (gtid < NCTA) g_flags[gtid * 64] = 0;
        if (gtid < BATCH * HID) g_ht[0][gtid] = __float2half_rn(h0[gtid]);
#pragma unroll
        for (int e = 0; e < 2; e++) {
            int idx = e * (DIM * GATES / 2) + gtid;
            int col = idx & 4095, k = idx >> 12;
            int g = col >> 10, rem = col & 1023;
            int c = rem >> 4, r2 = rem & 15, nhp = r2 >> 3, jj = r2 & 7;
            int np = c * 64 + nhp * 32 + g * 8 + jj;
            g_wrh[(size_t)np * DIM + k] = __float2half_rn(Wh[idx]);
        }
    }

    __shared__ uint32_t As[128][36];
    __shared__ uint32_t Bs[32][132];

    int tid = threadIdx.x, wid = tid >> 5, lane = tid & 31;
    int gid = lane >> 2, tig = lane & 3;
    int bm = blockIdx.y * 128, bn = blockIdx.x * 128;
    int wrow = (wid & 3) * 32, wcol = (wid >> 2) * 64;

    float acc[2][8][4];
#pragma unroll
    for (int i = 0; i < 2; i++)
#pragma unroll
        for (int j = 0; j < 8; j++)
#pragma unroll
            for (int k = 0; k < 4; k++) acc[i][j][k] = 0.f;

    float4 pa[4], pb[4];

#pragma unroll
    for (int u = 0; u < 4; u++) {
        int s = u * 256 + tid, r = s >> 3, c = (s & 7) * 4;
        pa[u] = *(const float4*)(x + (size_t)(bm + r) * DIM + c);
    }
#pragma unroll
    for (int u = 0; u < 4; u++) {
        int s = u * 256 + tid, r = s >> 5, c = (s & 31) * 4;
        pb[u] = *(const float4*)(Wi + (size_t)r * GATES + bn + c);
    }

    for (int k0 = 0; k0 < DIM; k0 += 32) {
#pragma unroll
        for (int u = 0; u < 4; u++) {
            int s = u * 256 + tid, r = s >> 3, c = (s & 7) * 4;
            As[r][c + 0] = f2tf(pa[u].x); As[r][c + 1] = f2tf(pa[u].y);
            As[r][c + 2] = f2tf(pa[u].z); As[r][c + 3] = f2tf(pa[u].w);
        }
#pragma unroll
        for (int u = 0; u < 4; u++) {
            int s = u * 256 + tid, r = s >> 5, c = (s & 31) * 4;
            Bs[r][c + 0] = f2tf(pb[u].x); Bs[r][c + 1] = f2tf(pb[u].y);
            Bs[r][c + 2] = f2tf(pb[u].z); Bs[r][c + 3] = f2tf(pb[u].w);
        }
        __syncthreads();

        if (k0 + 32 < DIM) {
#pragma unroll
            for (int u = 0; u < 4; u++) {
                int s = u * 256 + tid, r = s >> 3, c = (s & 7) * 4;
                pa[u] = *(const float4*)(x + (size_t)(bm + r) * DIM + k0 + 32 + c);
            }
#pragma unroll
            for (int u = 0; u < 4; u++) {
                int s = u * 256 + tid, r = s >> 5, c = (s & 31) * 4;
                pb[u] = *(const float4*)(Wi + (size_t)(k0 + 32 + r) * GATES + bn + c);
            }
        }

#pragma unroll
        for (int kk = 0; kk < 4; kk++) {
            int kb = kk * 8;
            uint32_t a[2][4];
#pragma unroll
            for (int mf = 0; mf < 2; mf++) {
                int m = wrow + mf * 16 + gid;
                a[mf][0] = As[m][kb + tig];
                a[mf][1] = As[m + 8][kb + tig];
                a[mf][2] = As[m][kb + tig + 4];
                a[mf][3] = As[m + 8][kb + tig + 4];
            }
#pragma unroll
            for (int nf = 0; nf < 8; nf++) {
                uint32_t b0 = Bs[kb + tig][wcol + nf * 8 + gid];
                uint32_t b1 = Bs[kb + tig + 4][wcol + nf * 8 + gid];
                mma_tf32(acc[0][nf], a[0][0], a[0][1], a[0][2], a[0][3], b0, b1);
                mma_tf32(acc[1][nf], a[1][0], a[1][1], a[1][2], a[1][3], b0, b1);
            }
        }
        __syncthreads();
    }

#pragma unroll
    for (int mf = 0; mf < 2; mf++)
#pragma unroll
        for (int nf = 0; nf < 8; nf++) {
            int row = bm + wrow + mf * 16 + gid;
            int col = bn + wcol + nf * 8 + 2 * tig;
            float bv0 = bias[col], bv1 = bias[col + 1];
            g_xg[(size_t)row * GATES + col]           = acc[mf][nf][0] + bv0;
            g_xg[(size_t)row * GATES + col + 1]       = acc[mf][nf][1] + bv1;
            g_xg[(size_t)(row + 8) * GATES + col]     = acc[mf][nf][2] + bv0;
            g_xg[(size_t)(row + 8) * GATES + col + 1] = acc[mf][nf][3] + bv1;
        }
}

// ---------------------------------------------------------------------------
// Kernel 2: persistent recurrence, fine-grained producer flags.
// CTA = (c = bid>>1, mg = bid&1): batch rows [mg*32,+32) x h-cols [c*16,+16)
// x 4 gates (N=64, gate-interleaved per nh-half).
// Warps: (ksp = wid>>1, nh = wid&1). Owners = warps 0-3 (mfh=wid>>1, nh=wid&1).
// Pollers = warps 4-7: thread p stages producer (pc = p>>1, mg)'s h columns
// for row-half (p&1) as soon as that producer's flag publishes.
// Reduce buffer layout: red[warp][chunk][lane] float4 -> 16B aligned,
// conflict-free, 32 KB total.
// ---------------------------------------------------------------------------
#define BBYTES 131072                  // B: 64 n-rows x 2048 B
#define ABYTES 65536                   // A: 32 rows x 2048 B (full K=1024)
#define REDOFF (BBYTES + ABYTES)       // 196608
#define PERSIST_SMEM (REDOFF + 8 * 8 * 32 * 16)   // 229376 <= 232448

__global__ __launch_bounds__(256, 1) void lstm_persist(const float* __restrict__ c0,
                                                       float* __restrict__ out) {
    extern __shared__ uint32_t sm[];
    char* smc = (char*)sm;
    uint32_t sbase = smem_u32(sm);
    float* red = (float*)(smc + REDOFF);   // [warp(8)][chunk(8)][lane(32)] float4

    int tid = threadIdx.x, wid = tid >> 5, lane = tid & 31;
    int gid = lane >> 2, tig = lane & 3;
    int cta = blockIdx.x;
    int c = cta >> 1, mg = cta & 1;
    int nh = wid & 1, ksp = wid >> 1;
    int n0 = c * 64;

    // ---- stationary B fill: 64 rows x 2048 B, XOR swizzled ----
#pragma unroll 4
    for (int u = 0; u < 32; u++) {
        int idx = u * 256 + tid;
        int n = idx >> 7, seg = idx & 127;
        uint4 v = *(const uint4*)((const char*)g_wrh + ((size_t)(n0 + n) * DIM + seg * 8) * 2);
        *(uint4*)(smc + n * 2048 + ((seg * 16) ^ ((n & 7) * 16))) = v;
    }

    // ---- ldmatrix lane addressing ----
    int tl = lane >> 3, ri = lane & 7;
    uint32_t khalf = (uint32_t)((tl >> 1) * 16);
    int rowA0 = (tl & 1) * 8 + ri, rowA1 = rowA0 + 16;
    uint32_t aOff0 = (uint32_t)(BBYTES + rowA0 * 2048), aSw0 = (uint32_t)((rowA0 & 7) * 16);
    uint32_t aOff1 = (uint32_t)(BBYTES + rowA1 * 2048), aSw1 = (uint32_t)((rowA1 & 7) * 16);
    int nrowB0 = nh * 32 + ((lane >> 4) & 1) * 8 + ri, nrowB1 = nrowB0 + 16;
    uint32_t kbB = (uint32_t)(((lane >> 3) & 1) * 16);
    uint32_t bOff0 = (uint32_t)(nrowB0 * 2048), bSw0 = (uint32_t)((nrowB0 & 7) * 16);
    uint32_t bOff1 = (uint32_t)(nrowB1 * 2048), bSw1 = (uint32_t)((nrowB1 & 7) * 16);

    // ---- owner state (warps 0-3): (mfh, onh) ----
    float creg[4];
    float xv[16];
    int orow = 0, ocolg = 0;
    if (wid < 4) {
        int mfh = wid >> 1, onh = wid & 1;
        orow = mg * 32 + mfh * 16 + gid;           // + rr*8
        ocolg = c * 16 + onh * 8 + tig * 2;        // + cc
#pragma unroll
        for (int rr = 0; rr < 2; rr++)
#pragma unroll
            for (int cc = 0; cc < 2; cc++)
                creg[rr * 2 + cc] = c0[(size_t)(orow + rr * 8) * HID + ocolg + cc];
#pragma unroll
        for (int g = 0; g < 4; g++)
#pragma unroll
            for (int rr = 0; rr < 2; rr++)
#pragma unroll
                for (int cc = 0; cc < 2; cc++)
                    xv[g * 4 + rr * 2 + cc] =
                        g_xg[(size_t)(orow + rr * 8) * GATES + g * 1024 + ocolg + cc];
    }

    // ---- poller state (warps 4-7) ----
    int pt = tid - 128;                 // 0..127
    int pc = pt >> 1, ph = pt & 1;      // producer col-CTA, row-half
    const unsigned* myflag = &g_flags[(pc * 2 + mg) * 64];

    // ---- pre-stage A(0) from g_ht[0] (flags trivially satisfied) ----
    if (wid >= 4) {
        const __half* hs = g_ht[0];
#pragma unroll
        for (int r = 0; r < 16; r++) {
            int row = mg * 32 + ph * 16 + r;
            int rs = ph * 16 + r;
            const uint4* src = (const uint4*)(hs + (size_t)row * HID + pc * 16);
            uint4 v0 = src[0], v1 = src[1];
            uint32_t ks = (uint32_t)(pc * 32), sw = (uint32_t)((rs & 7) * 16);
            *(uint4*)(smc + BBYTES + rs * 2048 + (ks ^ sw)) = v0;
            *(uint4*)(smc + BBYTES + rs * 2048 + ((ks + 16) ^ sw)) = v1;
        }
    }
    __syncthreads();

    for (int t = 0; t < T_STEPS; t++) {
        // ---- MMA phase: all 8 warps, full K, 4-way ksp split ----
        float acc[2][4][4];
#pragma unroll
        for (int i = 0; i < 2; i++)
#pragma unroll
            for (int j = 0; j < 4; j++)
#pragma unroll
                for (int k = 0; k < 4; k++) acc[i][j][k] = 0.f;

#pragma unroll
        for (int kq = 0; kq < 16; kq++) {
            uint32_t kbyte = (uint32_t)((kq * 4 + ksp) * 32);
            uint32_t a0[4], a1[4], bq[8];
            LDSM4(a0[0], a0[1], a0[2], a0[3], sbase + aOff0 + ((kbyte + khalf) ^ aSw0));
            LDSM4(a1[0], a1[1], a1[2], a1[3], sbase + aOff1 + ((kbyte + khalf) ^ aSw1));
            uint32_t kB = kbyte + kbB;
            LDSM4(bq[0], bq[1], bq[2], bq[3], sbase + bOff0 + (kB ^ bSw0));
            LDSM4(bq[4], bq[5], bq[6], bq[7], sbase + bOff1 + (kB ^ bSw1));
            mma_f16(acc[0][0], a0[0], a0[1], a0[2], a0[3], bq[0], bq[1]);
            mma_f16(acc[0][1], a0[0], a0[1], a0[2], a0[3], bq[2], bq[3]);
            mma_f16(acc[0][2], a0[0], a0[1], a0[2], a0[3], bq[4], bq[5]);
            mma_f16(acc[0][3], a0[0], a0[1], a0[2], a0[3], bq[6], bq[7]);
            mma_f16(acc[1][0], a1[0], a1[1], a1[2], a1[3], bq[0], bq[1]);
            mma_f16(acc[1][1], a1[0], a1[1], a1[2], a1[3], bq[2], bq[3]);
            mma_f16(acc[1][2], a1[0], a1[1], a1[2], a1[3], bq[4], bq[5]);
            mma_f16(acc[1][3], a1[0], a1[1], a1[2], a1[3], bq[6], bq[7]);
        }

        // ---- all warps store partials: red[wid][chunk][lane], 16B aligned ----
        {
            float* rp = red + (size_t)wid * 1024 + lane * 4;
#pragma unroll
            for (int mf = 0; mf < 2; mf++)
#pragma unroll
                for (int nf = 0; nf < 4; nf++)
                    *(float4*)(rp + (mf * 4 + nf) * 128) = *(const float4*)acc[mf][nf];
        }
        __syncthreads();   // MMA + partial stores complete; A region free

        if (wid < 4) {
            int mfh = wid >> 1, onh = wid & 1;
            // own ksp contribution lives in acc[mfh]; add the other 3 from red
            float s[4][4];
#pragma unroll
            for (int nf = 0; nf < 4; nf++)
#pragma unroll
                for (int k = 0; k < 4; k++) s[nf][k] = acc[mfh][nf][k];
#pragma unroll
            for (int sp = 0; sp < 4; sp++) {
                if (sp == ksp) continue;
                const float* rp = red + (size_t)(sp * 2 + onh) * 1024 + lane * 4;
#pragma unroll
                for (int nf = 0; nf < 4; nf++) {
                    float4 v = *(const float4*)(rp + (mfh * 4 + nf) * 128);
                    s[nf][0] += v.x; s[nf][1] += v.y; s[nf][2] += v.z; s[nf][3] += v.w;
                }
            }

            // fused LSTM epilogue; fp16 h stores (release path), packed half2
            __half* hnext = g_ht[(t + 1) & 1];
            float hv[4];
#pragma unroll
            for (int rr = 0; rr < 2; rr++) {
                float h0v = 0.f, h1v = 0.f;
#pragma unroll
                for (int cc = 0; cc < 2; cc++) {
                    int ci = rr * 2 + cc;
                    float iv = fsig(s[0][ci] + xv[ci]);
                    float fv = fsig(s[1][ci] + xv[4 + ci]);
                    float gv = ftanh(s[2][ci] + xv[8 + ci]);
                    float ov = fsig(s[3][ci] + xv[12 + ci]);
                    float cv = fv * creg[ci] + iv * gv;
                    creg[ci] = cv;
                    float h = ov * ftanh(cv);
                    hv[ci] = h;
                    if (cc == 0) h0v = h; else h1v = h;
                }
                *(__half2*)(hnext + (size_t)(orow + rr * 8) * HID + ocolg) =
                    __floats2half2_rn(h0v, h1v);
            }

            asm volatile("bar.sync 1, 128;" ::: "memory");   // owner warps only
            if (tid == 0 && t + 1 < T_STEPS)
                st_rel(&g_flags[cta * 64], (unsigned)(t + 1));

            // fp32 out stores + next xg prefetch (off the release path)
            float* h_out = out + (size_t)t * BATCH * HID;
#pragma unroll
            for (int rr = 0; rr < 2; rr++)
                *(float2*)(h_out + (size_t)(orow + rr * 8) * HID + ocolg) =
                    make_float2(hv[rr * 2], hv[rr * 2 + 1]);

            if (t + 1 < T_STEPS) {
                const float* xg_n = g_xg + (size_t)(t + 1) * BATCH * GATES;
#pragma unroll
                for (int g = 0; g < 4; g++)
#pragma unroll
                    for (int rr = 0; rr < 2; rr++)
#pragma unroll
                        for (int cc = 0; cc < 2; cc++)
                            xv[g * 4 + rr * 2 + cc] =
                                xg_n[(size_t)(orow + rr * 8) * GATES + g * 1024 + ocolg + cc];
            }
        } else if (t + 1 < T_STEPS) {
            // poller-stager: wait for MY producer only, then stage its columns
            unsigned tgt = (unsigned)(t + 1);
            while (ld_acq(myflag) < tgt) { }
            const __half* hs = g_ht[(t + 1) & 1];
#pragma unroll
            for (int r = 0; r < 16; r++) {
                int row = mg * 32 + ph * 16 + r;
                int rs = ph * 16 + r;
                const uint4* src = (const uint4*)(hs + (size_t)row * HID + pc * 16);
                uint4 v0 = src[0], v1 = src[1];
                uint32_t ks = (uint32_t)(pc * 32), sw = (uint32_t)((rs & 7) * 16);
                *(uint4*)(smc + BBYTES + rs * 2048 + (ks ^ sw)) = v0;
                *(uint4*)(smc + BBYTES + rs * 2048 + ((ks + 16) ^ sw)) = v1;
            }
        }
        __syncthreads();   // A(t+1) staged; owners done -> next MMA phase
    }
}

// ---------------------------------------------------------------------------
extern "C" void kernel_launch(void* const* d_in, const int* in_sizes, int n_in,
                              void* d_out, int out_size) {
    const float* x  = (const float*)d_in[0];   // [T, B, D]
    const float* c0 = (const float*)d_in[1];   // [B, H]
    const float* h0 = (const float*)d_in[2];   // [B, H]
    const float* Wi = (const float*)d_in[3];   // [D, 4H]
    const float* Wh = (const float*)d_in[4];   // [H, 4H]
    const float* b  = (const float*)d_in[5];   // [4H]
    float* out = (float*)d_out;                // [T, B, H]

    cudaFuncSetAttribute(lstm_persist, cudaFuncAttributeMaxDynamicSharedMemorySize,
                         PERSIST_SMEM);

    // Input projection + fused prep
    dim3 g1(GATES / 128, (T_STEPS * BATCH) / 128);
    xg_gemm_mma<<<g1, 256>>>(x, Wi, b, Wh, h0);

    // Persistent recurrence: one launch, all 512 steps
    lstm_persist<<<NCTA, 256, PERSIST_SMEM>>>(c0, out);
}

// round 10
// speedup vs baseline: 6.5215x; 1.3681x over previous
#include <cuda_runtime.h>
#include <cuda_fp16.h>
#include <math.h>
#include <stdint.h>

#define T_STEPS 512
#define BATCH   64
#define DIM     1024
#define HID     1024
#define GATES   4096
#define NCTA    128

// Scratch (__device__ globals: allocation-free rule)
__device__ float    g_xg[(size_t)T_STEPS * BATCH * GATES]; // x@Wi + b
__device__ __half   g_wrh[(size_t)GATES * DIM];            // Wh reordered [n'][k], fp16
__device__ uint32_t g_hf[2][4 * 64 * 32 * 4];              // h in A-frag layout, ping-pong
__device__ unsigned g_flags[NCTA * 64];                    // per-CTA flag, 256B stride

#define HFBYTES 131072   // one g_hf buffer: 4 m-blocks x 64 q-blocks x 32 lanes x 16B

// ---------------------------------------------------------------------------
// Helpers
// ---------------------------------------------------------------------------
__device__ __forceinline__ uint32_t f2tf(float v) {
    uint32_t u;
    asm("cvt.rna.tf32.f32 %0, %1;" : "=r"(u) : "f"(v));
    return u;
}

__device__ __forceinline__ void mma_tf32(float* c,
                                         uint32_t a0, uint32_t a1, uint32_t a2, uint32_t a3,
                                         uint32_t b0, uint32_t b1) {
    asm volatile(
        "mma.sync.aligned.m16n8k8.row.col.f32.tf32.tf32.f32 "
        "{%0,%1,%2,%3}, {%4,%5,%6,%7}, {%8,%9}, {%0,%1,%2,%3};"
        : "+f"(c[0]), "+f"(c[1]), "+f"(c[2]), "+f"(c[3])
        : "r"(a0), "r"(a1), "r"(a2), "r"(a3), "r"(b0), "r"(b1));
}

__device__ __forceinline__ void mma_f16(float* c,
                                        uint32_t a0, uint32_t a1, uint32_t a2, uint32_t a3,
                                        uint32_t b0, uint32_t b1) {
    asm volatile(
        "mma.sync.aligned.m16n8k16.row.col.f32.f16.f16.f32 "
        "{%0,%1,%2,%3}, {%4,%5,%6,%7}, {%8,%9}, {%0,%1,%2,%3};"
        : "+f"(c[0]), "+f"(c[1]), "+f"(c[2]), "+f"(c[3])
        : "r"(a0), "r"(a1), "r"(a2), "r"(a3), "r"(b0), "r"(b1));
}

__device__ __forceinline__ unsigned ld_acq(const unsigned* p) {
    unsigned v;
    asm volatile("ld.acquire.gpu.global.u32 %0, [%1];" : "=r"(v) : "l"(p));
    return v;
}
__device__ __forceinline__ void st_rel(unsigned* p, unsigned v) {
    asm volatile("st.release.gpu.global.u32 [%0], %1;" :: "l"(p), "r"(v) : "memory");
}

__device__ __forceinline__ uint4 ldcg128(const void* p) {
    uint4 v;
    asm volatile("ld.global.cg.v4.u32 {%0,%1,%2,%3}, [%4];"
                 : "=r"(v.x), "=r"(v.y), "=r"(v.z), "=r"(v.w) : "l"(p));
    return v;
}

__device__ __forceinline__ uint32_t smem_u32(const void* p) {
    uint32_t a;
    asm("{ .reg .u64 t; cvta.to.shared.u64 t, %1; cvt.u32.u64 %0, t; }" : "=r"(a) : "l"(p));
    return a;
}

__device__ __forceinline__ float fsig(float x) { return 1.f / (1.f + __expf(-x)); }
__device__ __forceinline__ float ftanh(float x) {
    float e = __expf(-2.f * fabsf(x));
    float r = (1.f - e) / (1.f + e);
    return x < 0.f ? -r : r;
}

#define LDSM4(r0, r1, r2, r3, addr) \
    asm volatile("ldmatrix.sync.aligned.m8n8.x4.shared.b16 {%0,%1,%2,%3}, [%4];" \
                 : "=r"(r0), "=r"(r1), "=r"(r2), "=r"(r3) : "r"(addr))

// ---------------------------------------------------------------------------
// Kernel 1: xg = x @ Wi + b (tf32, known-good). Fused prep: Wh -> g_wrh
// (fp16, gate-interleaved: np = c*64 + nh*32 + g*8 + jj for
// col = g*1024 + c*16 + nh*8 + jj), h0 -> g_hf[0] (frag layout), reset flags.
// ---------------------------------------------------------------------------
__global__ __launch_bounds__(256) void xg_gemm_mma(const float* __restrict__ x,
                                                   const float* __restrict__ Wi,
                                                   const float* __restrict__ bias,
                                                   const float* __restrict__ Wh,
                                                   const float* __restrict__ h0) {
    {
        int gtid = (blockIdx.y * gridDim.x + blockIdx.x) * 256 + threadIdx.x;
        if (gtid < NCTA) g_flags[gtid * 64] = 0;
        if (gtid < 32768) {  // h0 -> frag layout, one half2 per thread
            int row = gtid >> 9;         // 0..63
            int col = (gtid & 511) * 2;  // even col
            int m = row >> 4, q = col >> 4, kin = col & 15;
            int lane = ((row & 7) << 2) | ((kin & 7) >> 1);
            int reg = ((row & 15) >> 3) | ((kin >> 3) << 1);
            __half2 hh = __floats2half2_rn(h0[row * HID + col], h0[row * HID + col + 1]);
            *(uint32_t*)((char*)g_hf + ((size_t)((m * 64 + q) * 32 + lane)) * 16 + reg * 4) =
                *(uint32_t*)&hh;
        }
#pragma unroll
        for (int e = 0; e < 2; e++) {
            int idx = e * (DIM * GATES / 2) + gtid;
            int col = idx & 4095, k = idx >> 12;
            int g = col >> 10, rem = col & 1023;
            int c = rem >> 4, r2 = rem & 15, nhp = r2 >> 3, jj = r2 & 7;
            int np = c * 64 + nhp * 32 + g * 8 + jj;
            g_wrh[(size_t)np * DIM + k] = __float2half_rn(Wh[idx]);
        }
    }

    __shared__ uint32_t As[128][36];
    __shared__ uint32_t Bs[32][132];

    int tid = threadIdx.x, wid = tid >> 5, lane = tid & 31;
    int gid = lane >> 2, tig = lane & 3;
    int bm = blockIdx.y * 128, bn = blockIdx.x * 128;
    int wrow = (wid & 3) * 32, wcol = (wid >> 2) * 64;

    float acc[2][8][4];
#pragma unroll
    for (int i = 0; i < 2; i++)
#pragma unroll
        for (int j = 0; j < 8; j++)
#pragma unroll
            for (int k = 0; k < 4; k++) acc[i][j][k] = 0.f;

    float4 pa[4], pb[4];

#pragma unroll
    for (int u = 0; u < 4; u++) {
        int s = u * 256 + tid, r = s >> 3, cc = (s & 7) * 4;
        pa[u] = *(const float4*)(x + (size_t)(bm + r) * DIM + cc);
    }
#pragma unroll
    for (int u = 0; u < 4; u++) {
        int s = u * 256 + tid, r = s >> 5, cc = (s & 31) * 4;
        pb[u] = *(const float4*)(Wi + (size_t)r * GATES + bn + cc);
    }

    for (int k0 = 0; k0 < DIM; k0 += 32) {
#pragma unroll
        for (int u = 0; u < 4; u++) {
            int s = u * 256 + tid, r = s >> 3, cc = (s & 7) * 4;
            As[r][cc + 0] = f2tf(pa[u].x); As[r][cc + 1] = f2tf(pa[u].y);
            As[r][cc + 2] = f2tf(pa[u].z); As[r][cc + 3] = f2tf(pa[u].w);
        }
#pragma unroll
        for (int u = 0; u < 4; u++) {
            int s = u * 256 + tid, r = s >> 5, cc = (s & 31) * 4;
            Bs[r][cc + 0] = f2tf(pb[u].x); Bs[r][cc + 1] = f2tf(pb[u].y);
            Bs[r][cc + 2] = f2tf(pb[u].z); Bs[r][cc + 3] = f2tf(pb[u].w);
        }
        __syncthreads();

        if (k0 + 32 < DIM) {
#pragma unroll
            for (int u = 0; u < 4; u++) {
                int s = u * 256 + tid, r = s >> 3, cc = (s & 7) * 4;
                pa[u] = *(const float4*)(x + (size_t)(bm + r) * DIM + k0 + 32 + cc);
            }
#pragma unroll
            for (int u = 0; u < 4; u++) {
                int s = u * 256 + tid, r = s >> 5, cc = (s & 31) * 4;
                pb[u] = *(const float4*)(Wi + (size_t)(k0 + 32 + r) * GATES + bn + cc);
            }
        }

#pragma unroll
        for (int kk = 0; kk < 4; kk++) {
            int kb = kk * 8;
            uint32_t a[2][4];
#pragma unroll
            for (int mf = 0; mf < 2; mf++) {
                int m = wrow + mf * 16 + gid;
                a[mf][0] = As[m][kb + tig];
                a[mf][1] = As[m + 8][kb + tig];
                a[mf][2] = As[m][kb + tig + 4];
                a[mf][3] = As[m + 8][kb + tig + 4];
            }
#pragma unroll
            for (int nf = 0; nf < 8; nf++) {
                uint32_t b0 = Bs[kb + tig][wcol + nf * 8 + gid];
                uint32_t b1 = Bs[kb + tig + 4][wcol + nf * 8 + gid];
                mma_tf32(acc[0][nf], a[0][0], a[0][1], a[0][2], a[0][3], b0, b1);
                mma_tf32(acc[1][nf], a[1][0], a[1][1], a[1][2], a[1][3], b0, b1);
            }
        }
        __syncthreads();
    }

#pragma unroll
    for (int mf = 0; mf < 2; mf++)
#pragma unroll
        for (int nf = 0; nf < 8; nf++) {
            int row = bm + wrow + mf * 16 + gid;
            int col = bn + wcol + nf * 8 + 2 * tig;
            float bv0 = bias[col], bv1 = bias[col + 1];
            g_xg[(size_t)row * GATES + col]           = acc[mf][nf][0] + bv0;
            g_xg[(size_t)row * GATES + col + 1]       = acc[mf][nf][1] + bv1;
            g_xg[(size_t)(row + 8) * GATES + col]     = acc[mf][nf][2] + bv0;
            g_xg[(size_t)(row + 8) * GATES + col + 1] = acc[mf][nf][3] + bv1;
        }
}

// ---------------------------------------------------------------------------
// Kernel 2: persistent recurrence, A direct-from-gmem in fragment layout.
// CTA (c = bid>>1, mg = bid&1): batch rows [mg*32,+32) x h-cols [c*16,+16) x
// 4 gates (N=64). 8 warps = 8-way K-split (warp ks owns k16 blocks
// q in [ks*8, ks*8+8)). Per-warp flag waits on its 8 producers only.
// B resident in smem (128 KB); reduce buffer 68 KB; no A smem tile.
// ---------------------------------------------------------------------------
#define BBYTES 131072                 // B: 64 n-rows x 2048 B, XOR swizzled
#define CHSZ   544                    // reduce chunk stride (512 data + pad)
#define RWSZ   (16 * CHSZ)            // per-warp reduce: 16 chunks (mf*8+nf)
#define REDOFF BBYTES
#define PERSIST_SMEM (REDOFF + 8 * RWSZ)   // 131072 + 69632 = 200704

__global__ __launch_bounds__(256, 1) void lstm_persist(const float* __restrict__ c0,
                                                       float* __restrict__ out) {
    extern __shared__ uint32_t sm[];
    char* smc = (char*)sm;
    uint32_t sbase = smem_u32(sm);

    int tid = threadIdx.x, wid = tid >> 5, lane = tid & 31;
    int cta = blockIdx.x;
    int c = cta >> 1, mg = cta & 1;
    int ks = wid;                      // this warp's K-eighth
    int n0 = c * 64;

    // ---- stationary B fill: 64 rows x 2048 B, XOR swizzled ----
#pragma unroll 4
    for (int u = 0; u < 32; u++) {
        int idx = u * 256 + tid;
        int n = idx >> 7, seg = idx & 127;
        uint4 v = *(const uint4*)((const char*)g_wrh + ((size_t)(n0 + n) * DIM + seg * 8) * 2);
        *(uint4*)(smc + n * 2048 + ((seg * 16) ^ ((n & 7) * 16))) = v;
    }

    // ---- B ldmatrix addressing (4 LDSM4 per k16: n-rows 0,16,32,48) ----
    int ri = lane & 7;
    uint32_t kbB = (uint32_t)(((lane >> 3) & 1) * 16);
    uint32_t bOff[4], bSw[4];
#pragma unroll
    for (int j = 0; j < 4; j++) {
        int nrow = j * 16 + ((lane >> 4) & 1) * 8 + ri;
        bOff[j] = (uint32_t)(nrow * 2048);
        bSw[j] = (uint32_t)((nrow & 7) * 16);
    }

    // ---- epilogue constants (every thread owns 2 h-cells) ----
    int rl = wid * 4 + (lane >> 3);        // local row 0..31
    int rgl = mg * 32 + rl;                // global batch row
    int nh_t = (lane >> 2) & 1;
    int jj0 = (lane & 3) * 2;
    int hc = c * 16 + nh_t * 8 + jj0;      // global h col (pair hc, hc+1)
    int mfE = rl >> 4, rf = rl & 15;
    int dlane = (rf & 7) * 4 + (jj0 >> 1);
    int fb = (rf >> 3) * 2;                // D-frag float index base
    int regE = (rf >> 3) | (nh_t << 1);    // A-frag reg index for h store
    uint32_t hfStoreOff =
        (uint32_t)(((mg * 2 + mfE) * 64 + c) * 32 + dlane) * 16 + regE * 4;

    float creg[2];
    creg[0] = c0[(size_t)rgl * HID + hc];
    creg[1] = c0[(size_t)rgl * HID + hc + 1];
    float xv[8];
#pragma unroll
    for (int g = 0; g < 4; g++) {
        xv[g * 2 + 0] = g_xg[(size_t)rgl * GATES + g * 1024 + hc];
        xv[g * 2 + 1] = g_xg[(size_t)rgl * GATES + g * 1024 + hc + 1];
    }
    __syncthreads();   // B resident

    for (int t = 0; t < T_STEPS; t++) {
        // ---- per-warp wait: only THIS warp's 8 producers ----
        if (t > 0) {
            if (lane < 8) {
                const unsigned* fp = &g_flags[(((ks * 8 + lane) << 1) | mg) << 6];
                while (ld_acq(fp) < (unsigned)t) { }
            }
            __syncwarp();
        }

        const char* hb = (const char*)g_hf + (size_t)(t & 1) * HFBYTES;

        // ---- A prefetch pipeline (depth 3), frags direct from gmem ----
        uint4 pa[3][2];
#pragma unroll
        for (int p = 0; p < 3; p++) {
            int q = ks * 8 + p;
#pragma unroll
            for (int mf = 0; mf < 2; mf++)
                pa[p][mf] = ldcg128(hb +
                    (size_t)(((mg * 2 + mf) * 64 + q) * 32 + lane) * 16);
        }

        float acc[2][8][4];
#pragma unroll
        for (int i = 0; i < 2; i++)
#pragma unroll
            for (int j = 0; j < 8; j++)
#pragma unroll
                for (int k = 0; k < 4; k++) acc[i][j][k] = 0.f;

#pragma unroll
        for (int kq = 0; kq < 8; kq++) {
            uint4 A0 = pa[kq % 3][0], A1 = pa[kq % 3][1];
            if (kq < 5) {
                int qn = ks * 8 + kq + 3;
#pragma unroll
                for (int mf = 0; mf < 2; mf++)
                    pa[kq % 3][mf] = ldcg128(hb +
                        (size_t)(((mg * 2 + mf) * 64 + qn) * 32 + lane) * 16);
            }
            int q = ks * 8 + kq;
            uint32_t kB = (uint32_t)(q * 32) + kbB;
            uint32_t bq[16];
#pragma unroll
            for (int j = 0; j < 4; j++)
                LDSM4(bq[j * 4], bq[j * 4 + 1], bq[j * 4 + 2], bq[j * 4 + 3],
                      sbase + bOff[j] + (kB ^ bSw[j]));
#pragma unroll
            for (int nf = 0; nf < 8; nf++) {
                mma_f16(acc[0][nf], A0.x, A0.y, A0.z, A0.w, bq[nf * 2], bq[nf * 2 + 1]);
                mma_f16(acc[1][nf], A1.x, A1.y, A1.z, A1.w, bq[nf * 2], bq[nf * 2 + 1]);
            }
        }

        // ---- partial stores: red[warp][mf*8+nf][lane] float4 ----
        {
            char* rp = smc + REDOFF + wid * RWSZ + lane * 16;
#pragma unroll
            for (int mf = 0; mf < 2; mf++)
#pragma unroll
                for (int nf = 0; nf < 8; nf++)
                    *(float4*)(rp + (mf * 8 + nf) * CHSZ) = *(const float4*)acc[mf][nf];
        }
        __syncthreads();

        // ---- reduce (8-way) + fused epilogue, ALL 256 threads ----
        float sg[4][2];
#pragma unroll
        for (int g = 0; g < 4; g++) { sg[g][0] = 0.f; sg[g][1] = 0.f; }
#pragma unroll
        for (int w = 0; w < 8; w++) {
            const char* rp = smc + REDOFF + w * RWSZ +
                             (mfE * 8 + nh_t * 4) * CHSZ + dlane * 16 + fb * 4;
#pragma unroll
            for (int g = 0; g < 4; g++) {
                float2 v = *(const float2*)(rp + g * CHSZ);
                sg[g][0] += v.x; sg[g][1] += v.y;
            }
        }

        float hv[2];
#pragma unroll
        for (int cc = 0; cc < 2; cc++) {
            float iv = fsig(sg[0][cc] + xv[cc]);
            float fv = fsig(sg[1][cc] + xv[2 + cc]);
            float gv = ftanh(sg[2][cc] + xv[4 + cc]);
            float ov = fsig(sg[3][cc] + xv[6 + cc]);
            float cv = fv * creg[cc] + iv * gv;
            creg[cc] = cv;
            hv[cc] = ov * ftanh(cv);
        }

        // h -> frag layout (one STG.32) for step t+1 consumers
        {
            __half2 hh = __floats2half2_rn(hv[0], hv[1]);
            *(uint32_t*)((char*)g_hf + (size_t)((t + 1) & 1) * HFBYTES + hfStoreOff) =
                *(uint32_t*)&hh;
        }
        __syncthreads();   // all epilogue stores done; red consumable next step
        if (tid == 0 && t + 1 < T_STEPS)
            st_rel(&g_flags[cta << 6], (unsigned)(t + 1));

        // fp32 output + next xg prefetch (off the release path)
        *(float2*)(out + (size_t)t * BATCH * HID + (size_t)rgl * HID + hc) =
            make_float2(hv[0], hv[1]);
        if (t + 1 < T_STEPS) {
            const float* xn = g_xg + (size_t)(t + 1) * BATCH * GATES + (size_t)rgl * GATES;
#pragma unroll
            for (int g = 0; g < 4; g++) {
                xv[g * 2 + 0] = xn[g * 1024 + hc];
                xv[g * 2 + 1] = xn[g * 1024 + hc + 1];
            }
        }
    }
}

// ---------------------------------------------------------------------------
extern "C" void kernel_launch(void* const* d_in, const int* in_sizes, int n_in,
                              void* d_out, int out_size) {
    const float* x  = (const float*)d_in[0];   // [T, B, D]
    const float* c0 = (const float*)d_in[1];   // [B, H]
    const float* h0 = (const float*)d_in[2];   // [B, H]
    const float* Wi = (const float*)d_in[3];   // [D, 4H]
    const float* Wh = (const float*)d_in[4];   // [H, 4H]
    const float* b  = (const float*)d_in[5];   // [4H]
    float* out = (float*)d_out;                // [T, B, H]

    cudaFuncSetAttribute(lstm_persist, cudaFuncAttributeMaxDynamicSharedMemorySize,
                         PERSIST_SMEM);

    // Input projection + fused prep (Wh->fp16 reorder, h0->frags, flag reset)
    dim3 g1(GATES / 128, (T_STEPS * BATCH) / 128);
    xg_gemm_mma<<<g1, 256>>>(x, Wi, b, Wh, h0);

    // Persistent recurrence: one launch, all 512 steps
    lstm_persist<<<NCTA, 256, PERSIST_SMEM>>>(c0, out);
}

// round 11
// speedup vs baseline: 6.5512x; 1.0046x over previous
#include <cuda_runtime.h>
#include <cuda_fp16.h>
#include <math.h>
#include <stdint.h>

#define T_STEPS 512
#define BATCH   64
#define DIM     1024
#define HID     1024
#define GATES   4096
#define NCTA    128

// Scratch (__device__ globals: allocation-free rule)
__device__ float    g_xg[(size_t)T_STEPS * BATCH * GATES]; // x@Wi + b
__device__ __half   g_wrh[(size_t)GATES * DIM];            // Wh reordered [n'][k], fp16
__device__ uint32_t g_hf[2][4 * 64 * 32 * 4];              // h in A-frag layout, ping-pong
__device__ unsigned g_flags[NCTA * 64];                    // per-CTA flag, 256B stride

#define HFBYTES 131072   // one g_hf buffer: 4 m-blocks x 64 q-blocks x 32 lanes x 16B

// ---------------------------------------------------------------------------
// Helpers
// ---------------------------------------------------------------------------
__device__ __forceinline__ uint32_t f2tf(float v) {
    uint32_t u;
    asm("cvt.rna.tf32.f32 %0, %1;" : "=r"(u) : "f"(v));
    return u;
}

__device__ __forceinline__ void mma_tf32(float* c,
                                         uint32_t a0, uint32_t a1, uint32_t a2, uint32_t a3,
                                         uint32_t b0, uint32_t b1) {
    asm volatile(
        "mma.sync.aligned.m16n8k8.row.col.f32.tf32.tf32.f32 "
        "{%0,%1,%2,%3}, {%4,%5,%6,%7}, {%8,%9}, {%0,%1,%2,%3};"
        : "+f"(c[0]), "+f"(c[1]), "+f"(c[2]), "+f"(c[3])
        : "r"(a0), "r"(a1), "r"(a2), "r"(a3), "r"(b0), "r"(b1));
}

__device__ __forceinline__ void mma_f16(float* c,
                                        uint32_t a0, uint32_t a1, uint32_t a2, uint32_t a3,
                                        uint32_t b0, uint32_t b1) {
    asm volatile(
        "mma.sync.aligned.m16n8k16.row.col.f32.f16.f16.f32 "
        "{%0,%1,%2,%3}, {%4,%5,%6,%7}, {%8,%9}, {%0,%1,%2,%3};"
        : "+f"(c[0]), "+f"(c[1]), "+f"(c[2]), "+f"(c[3])
        : "r"(a0), "r"(a1), "r"(a2), "r"(a3), "r"(b0), "r"(b1));
}

__device__ __forceinline__ unsigned ld_acq(const unsigned* p) {
    unsigned v;
    asm volatile("ld.acquire.gpu.global.u32 %0, [%1];" : "=r"(v) : "l"(p));
    return v;
}
__device__ __forceinline__ void st_rel(unsigned* p, unsigned v) {
    asm volatile("st.release.gpu.global.u32 [%0], %1;" :: "l"(p), "r"(v) : "memory");
}

__device__ __forceinline__ uint4 ldcg128(const void* p) {
    uint4 v;
    asm volatile("ld.global.cg.v4.u32 {%0,%1,%2,%3}, [%4];"
                 : "=r"(v.x), "=r"(v.y), "=r"(v.z), "=r"(v.w) : "l"(p));
    return v;
}

__device__ __forceinline__ uint32_t smem_u32(const void* p) {
    uint32_t a;
    asm("{ .reg .u64 t; cvta.to.shared.u64 t, %1; cvt.u32.u64 %0, t; }" : "=r"(a) : "l"(p));
    return a;
}

__device__ __forceinline__ float fsig(float x) { return 1.f / (1.f + __expf(-x)); }
__device__ __forceinline__ float ftanh(float x) {
    float e = __expf(-2.f * fabsf(x));
    float r = (1.f - e) / (1.f + e);
    return x < 0.f ? -r : r;
}

#define LDSM4(r0, r1, r2, r3, addr) \
    asm volatile("ldmatrix.sync.aligned.m8n8.x4.shared.b16 {%0,%1,%2,%3}, [%4];" \
                 : "=r"(r0), "=r"(r1), "=r"(r2), "=r"(r3) : "r"(addr))

// ---------------------------------------------------------------------------
// Kernel 1: xg = x @ Wi + b (tf32, known-good). Fused prep: Wh -> g_wrh
// (fp16, gate-interleaved: np = c*64 + nh*32 + g*8 + jj for
// col = g*1024 + c*16 + nh*8 + jj), h0 -> g_hf[0] (frag layout), reset flags.
// ---------------------------------------------------------------------------
__global__ __launch_bounds__(256) void xg_gemm_mma(const float* __restrict__ x,
                                                   const float* __restrict__ Wi,
                                                   const float* __restrict__ bias,
                                                   const float* __restrict__ Wh,
                                                   const float* __restrict__ h0) {
    {
        int gtid = (blockIdx.y * gridDim.x + blockIdx.x) * 256 + threadIdx.x;
        if (gtid < NCTA) g_flags[gtid * 64] = 0;
        if (gtid < 32768) {  // h0 -> frag layout, one half2 per thread
            int row = gtid >> 9;         // 0..63
            int col = (gtid & 511) * 2;  // even col
            int m = row >> 4, q = col >> 4, kin = col & 15;
            int lane = ((row & 7) << 2) | ((kin & 7) >> 1);
            int reg = ((row & 15) >> 3) | ((kin >> 3) << 1);
            __half2 hh = __floats2half2_rn(h0[row * HID + col], h0[row * HID + col + 1]);
            *(uint32_t*)((char*)g_hf + ((size_t)((m * 64 + q) * 32 + lane)) * 16 + reg * 4) =
                *(uint32_t*)&hh;
        }
#pragma unroll
        for (int e = 0; e < 2; e++) {
            int idx = e * (DIM * GATES / 2) + gtid;
            int col = idx & 4095, k = idx >> 12;
            int g = col >> 10, rem = col & 1023;
            int c = rem >> 4, r2 = rem & 15, nhp = r2 >> 3, jj = r2 & 7;
            int np = c * 64 + nhp * 32 + g * 8 + jj;
            g_wrh[(size_t)np * DIM + k] = __float2half_rn(Wh[idx]);
        }
    }

    __shared__ uint32_t As[128][36];
    __shared__ uint32_t Bs[32][132];

    int tid = threadIdx.x, wid = tid >> 5, lane = tid & 31;
    int gid = lane >> 2, tig = lane & 3;
    int bm = blockIdx.y * 128, bn = blockIdx.x * 128;
    int wrow = (wid & 3) * 32, wcol = (wid >> 2) * 64;

    float acc[2][8][4];
#pragma unroll
    for (int i = 0; i < 2; i++)
#pragma unroll
        for (int j = 0; j < 8; j++)
#pragma unroll
            for (int k = 0; k < 4; k++) acc[i][j][k] = 0.f;

    float4 pa[4], pb[4];

#pragma unroll
    for (int u = 0; u < 4; u++) {
        int s = u * 256 + tid, r = s >> 3, cc = (s & 7) * 4;
        pa[u] = *(const float4*)(x + (size_t)(bm + r) * DIM + cc);
    }
#pragma unroll
    for (int u = 0; u < 4; u++) {
        int s = u * 256 + tid, r = s >> 5, cc = (s & 31) * 4;
        pb[u] = *(const float4*)(Wi + (size_t)r * GATES + bn + cc);
    }

    for (int k0 = 0; k0 < DIM; k0 += 32) {
#pragma unroll
        for (int u = 0; u < 4; u++) {
            int s = u * 256 + tid, r = s >> 3, cc = (s & 7) * 4;
            As[r][cc + 0] = f2tf(pa[u].x); As[r][cc + 1] = f2tf(pa[u].y);
            As[r][cc + 2] = f2tf(pa[u].z); As[r][cc + 3] = f2tf(pa[u].w);
        }
#pragma unroll
        for (int u = 0; u < 4; u++) {
            int s = u * 256 + tid, r = s >> 5, cc = (s & 31) * 4;
            Bs[r][cc + 0] = f2tf(pb[u].x); Bs[r][cc + 1] = f2tf(pb[u].y);
            Bs[r][cc + 2] = f2tf(pb[u].z); Bs[r][cc + 3] = f2tf(pb[u].w);
        }
        __syncthreads();

        if (k0 + 32 < DIM) {
#pragma unroll
            for (int u = 0; u < 4; u++) {
                int s = u * 256 + tid, r = s >> 3, cc = (s & 7) * 4;
                pa[u] = *(const float4*)(x + (size_t)(bm + r) * DIM + k0 + 32 + cc);
            }
#pragma unroll
            for (int u = 0; u < 4; u++) {
                int s = u * 256 + tid, r = s >> 5, cc = (s & 31) * 4;
                pb[u] = *(const float4*)(Wi + (size_t)(k0 + 32 + r) * GATES + bn + cc);
            }
        }

#pragma unroll
        for (int kk = 0; kk < 4; kk++) {
            int kb = kk * 8;
            uint32_t a[2][4];
#pragma unroll
            for (int mf = 0; mf < 2; mf++) {
                int m = wrow + mf * 16 + gid;
                a[mf][0] = As[m][kb + tig];
                a[mf][1] = As[m + 8][kb + tig];
                a[mf][2] = As[m][kb + tig + 4];
                a[mf][3] = As[m + 8][kb + tig + 4];
            }
#pragma unroll
            for (int nf = 0; nf < 8; nf++) {
                uint32_t b0 = Bs[kb + tig][wcol + nf * 8 + gid];
                uint32_t b1 = Bs[kb + tig + 4][wcol + nf * 8 + gid];
                mma_tf32(acc[0][nf], a[0][0], a[0][1], a[0][2], a[0][3], b0, b1);
                mma_tf32(acc[1][nf], a[1][0], a[1][1], a[1][2], a[1][3], b0, b1);
            }
        }
        __syncthreads();
    }

#pragma unroll
    for (int mf = 0; mf < 2; mf++)
#pragma unroll
        for (int nf = 0; nf < 8; nf++) {
            int row = bm + wrow + mf * 16 + gid;
            int col = bn + wcol + nf * 8 + 2 * tig;
            float bv0 = bias[col], bv1 = bias[col + 1];
            g_xg[(size_t)row * GATES + col]           = acc[mf][nf][0] + bv0;
            g_xg[(size_t)row * GATES + col + 1]       = acc[mf][nf][1] + bv1;
            g_xg[(size_t)(row + 8) * GATES + col]     = acc[mf][nf][2] + bv0;
            g_xg[(size_t)(row + 8) * GATES + col + 1] = acc[mf][nf][3] + bv1;
        }
}

// ---------------------------------------------------------------------------
// Kernel 2: persistent recurrence, A direct-from-gmem in fragment layout.
// CTA (c = bid>>1, mg = bid&1): batch rows [mg*32,+32) x h-cols [c*16,+16) x
// 4 gates (N=64). 8 warps = 8-way K-split (warp ks owns k16 blocks
// q in [ks*8, ks*8+8)). Per-warp flag waits on its 8 producers only.
// B resident in smem (128 KB); reduce buffer 68 KB; no A smem tile.
// ---------------------------------------------------------------------------
#define BBYTES 131072                 // B: 64 n-rows x 2048 B, XOR swizzled
#define CHSZ   544                    // reduce chunk stride (512 data + pad)
#define RWSZ   (16 * CHSZ)            // per-warp reduce: 16 chunks (mf*8+nf)
#define REDOFF BBYTES
#define PERSIST_SMEM (REDOFF + 8 * RWSZ)   // 131072 + 69632 = 200704

__global__ __launch_bounds__(256, 1) void lstm_persist(const float* __restrict__ c0,
                                                       float* __restrict__ out) {
    extern __shared__ uint32_t sm[];
    char* smc = (char*)sm;
    uint32_t sbase = smem_u32(sm);

    int tid = threadIdx.x, wid = tid >> 5, lane = tid & 31;
    int cta = blockIdx.x;
    int c = cta >> 1, mg = cta & 1;
    int ks = wid;                      // this warp's K-eighth
    int n0 = c * 64;

    // ---- stationary B fill: 64 rows x 2048 B, XOR swizzled ----
#pragma unroll 4
    for (int u = 0; u < 32; u++) {
        int idx = u * 256 + tid;
        int n = idx >> 7, seg = idx & 127;
        uint4 v = *(const uint4*)((const char*)g_wrh + ((size_t)(n0 + n) * DIM + seg * 8) * 2);
        *(uint4*)(smc + n * 2048 + ((seg * 16) ^ ((n & 7) * 16))) = v;
    }

    // ---- B ldmatrix addressing (4 LDSM4 per k16: n-rows 0,16,32,48) ----
    int ri = lane & 7;
    uint32_t kbB = (uint32_t)(((lane >> 3) & 1) * 16);
    uint32_t bOff[4], bSw[4];
#pragma unroll
    for (int j = 0; j < 4; j++) {
        int nrow = j * 16 + ((lane >> 4) & 1) * 8 + ri;
        bOff[j] = (uint32_t)(nrow * 2048);
        bSw[j] = (uint32_t)((nrow & 7) * 16);
    }

    // ---- epilogue constants (every thread owns 2 h-cells) ----
    int rl = wid * 4 + (lane >> 3);        // local row 0..31
    int rgl = mg * 32 + rl;                // global batch row
    int nh_t = (lane >> 2) & 1;
    int jj0 = (lane & 3) * 2;
    int hc = c * 16 + nh_t * 8 + jj0;      // global h col (pair hc, hc+1)
    int mfE = rl >> 4, rf = rl & 15;
    int dlane = (rf & 7) * 4 + (jj0 >> 1);
    int fb = (rf >> 3) * 2;                // D-frag float index base
    int regE = (rf >> 3) | (nh_t << 1);    // A-frag reg index for h store
    uint32_t hfStoreOff =
        (uint32_t)(((mg * 2 + mfE) * 64 + c) * 32 + dlane) * 16 + regE * 4;

    float creg[2];
    creg[0] = c0[(size_t)rgl * HID + hc];
    creg[1] = c0[(size_t)rgl * HID + hc + 1];
    float xv[8];
#pragma unroll
    for (int g = 0; g < 4; g++) {
        xv[g * 2 + 0] = g_xg[(size_t)rgl * GATES + g * 1024 + hc];
        xv[g * 2 + 1] = g_xg[(size_t)rgl * GATES + g * 1024 + hc + 1];
    }
    __syncthreads();   // B resident

    for (int t = 0; t < T_STEPS; t++) {
        // ---- per-warp wait: only THIS warp's 8 producers ----
        if (t > 0) {
            if (lane < 8) {
                const unsigned* fp = &g_flags[(((ks * 8 + lane) << 1) | mg) << 6];
                while (ld_acq(fp) < (unsigned)t) { }
            }
            __syncwarp();
        }

        const char* hb = (const char*)g_hf + (size_t)(t & 1) * HFBYTES;

        // ---- A prefetch pipeline (depth 3), frags direct from gmem ----
        uint4 pa[3][2];
#pragma unroll
        for (int p = 0; p < 3; p++) {
            int q = ks * 8 + p;
#pragma unroll
            for (int mf = 0; mf < 2; mf++)
                pa[p][mf] = ldcg128(hb +
                    (size_t)(((mg * 2 + mf) * 64 + q) * 32 + lane) * 16);
        }

        float acc[2][8][4];
#pragma unroll
        for (int i = 0; i < 2; i++)
#pragma unroll
            for (int j = 0; j < 8; j++)
#pragma unroll
                for (int k = 0; k < 4; k++) acc[i][j][k] = 0.f;

#pragma unroll
        for (int kq = 0; kq < 8; kq++) {
            uint4 A0 = pa[kq % 3][0], A1 = pa[kq % 3][1];
            if (kq < 5) {
                int qn = ks * 8 + kq + 3;
#pragma unroll
                for (int mf = 0; mf < 2; mf++)
                    pa[kq % 3][mf] = ldcg128(hb +
                        (size_t)(((mg * 2 + mf) * 64 + qn) * 32 + lane) * 16);
            }
            int q = ks * 8 + kq;
            uint32_t kB = (uint32_t)(q * 32) + kbB;
            uint32_t bq[16];
#pragma unroll
            for (int j = 0; j < 4; j++)
                LDSM4(bq[j * 4], bq[j * 4 + 1], bq[j * 4 + 2], bq[j * 4 + 3],
                      sbase + bOff[j] + (kB ^ bSw[j]));
#pragma unroll
            for (int nf = 0; nf < 8; nf++) {
                mma_f16(acc[0][nf], A0.x, A0.y, A0.z, A0.w, bq[nf * 2], bq[nf * 2 + 1]);
                mma_f16(acc[1][nf], A1.x, A1.y, A1.z, A1.w, bq[nf * 2], bq[nf * 2 + 1]);
            }
        }

        // ---- partial stores: red[warp][mf*8+nf][lane] float4 ----
        {
            char* rp = smc + REDOFF + wid * RWSZ + lane * 16;
#pragma unroll
            for (int mf = 0; mf < 2; mf++)
#pragma unroll
                for (int nf = 0; nf < 8; nf++)
                    *(float4*)(rp + (mf * 8 + nf) * CHSZ) = *(const float4*)acc[mf][nf];
        }
        __syncthreads();

        // ---- reduce (8-way) + fused epilogue, ALL 256 threads ----
        float sg[4][2];
#pragma unroll
        for (int g = 0; g < 4; g++) { sg[g][0] = 0.f; sg[g][1] = 0.f; }
#pragma unroll
        for (int w = 0; w < 8; w++) {
            const char* rp = smc + REDOFF + w * RWSZ +
                             (mfE * 8 + nh_t * 4) * CHSZ + dlane * 16 + fb * 4;
#pragma unroll
            for (int g = 0; g < 4; g++) {
                float2 v = *(const float2*)(rp + g * CHSZ);
                sg[g][0] += v.x; sg[g][1] += v.y;
            }
        }

        float hv[2];
#pragma unroll
        for (int cc = 0; cc < 2; cc++) {
            float iv = fsig(sg[0][cc] + xv[cc]);
            float fv = fsig(sg[1][cc] + xv[2 + cc]);
            float gv = ftanh(sg[2][cc] + xv[4 + cc]);
            float ov = fsig(sg[3][cc] + xv[6 + cc]);
            float cv = fv * creg[cc] + iv * gv;
            creg[cc] = cv;
            hv[cc] = ov * ftanh(cv);
        }

        // h -> frag layout (one STG.32) for step t+1 consumers
        {
            __half2 hh = __floats2half2_rn(hv[0], hv[1]);
            *(uint32_t*)((char*)g_hf + (size_t)((t + 1) & 1) * HFBYTES + hfStoreOff) =
                *(uint32_t*)&hh;
        }
        __syncthreads();   // all epilogue stores done; red consumable next step
        if (tid == 0 && t + 1 < T_STEPS)
            st_rel(&g_flags[cta << 6], (unsigned)(t + 1));

        // fp32 output + next xg prefetch (off the release path)
        *(float2*)(out + (size_t)t * BATCH * HID + (size_t)rgl * HID + hc) =
            make_float2(hv[0], hv[1]);
        if (t + 1 < T_STEPS) {
            const float* xn = g_xg + (size_t)(t + 1) * BATCH * GATES + (size_t)rgl * GATES;
#pragma unroll
            for (int g = 0; g < 4; g++) {
                xv[g * 2 + 0] = xn[g * 1024 + hc];
                xv[g * 2 + 1] = xn[g * 1024 + hc + 1];
            }
        }
    }
}

// ---------------------------------------------------------------------------
extern "C" void kernel_launch(void* const* d_in, const int* in_sizes, int n_in,
                              void* d_out, int out_size) {
    const float* x  = (const float*)d_in[0];   // [T, B, D]
    const float* c0 = (const float*)d_in[1];   // [B, H]
    const float* h0 = (const float*)d_in[2];   // [B, H]
    const float* Wi = (const float*)d_in[3];   // [D, 4H]
    const float* Wh = (const float*)d_in[4];   // [H, 4H]
    const float* b  = (const float*)d_in[5];   // [4H]
    float* out = (float*)d_out;                // [T, B, H]

    cudaFuncSetAttribute(lstm_persist, cudaFuncAttributeMaxDynamicSharedMemorySize,
                         PERSIST_SMEM);

    // Input projection + fused prep (Wh->fp16 reorder, h0->frags, flag reset)
    dim3 g1(GATES / 128, (T_STEPS * BATCH) / 128);
    xg_gemm_mma<<<g1, 256>>>(x, Wi, b, Wh, h0);

    // Persistent recurrence: one launch, all 512 steps
    lstm_persist<<<NCTA, 256, PERSIST_SMEM>>>(c0, out);
}